// round 2
// baseline (speedup 1.0000x reference)
#include <cuda_runtime.h>
#include <math.h>

// ---------------- problem constants ----------------
#define TREL   5
#define HEADS  4
#define HID    128
#define INFEAT 256
#define OUTF   153
#define NSRC0  120000
#define NDST0  40000
#define NDST1  10000
#define E0     800000
#define E1     300000
#define NEG    0.2f
#define EPSV   1e-5

// ---------------- device scratch (static, allowed) ----------------
__device__ __align__(16) float g_H0  [TREL * NSRC0 * HID];
__device__ __align__(16) float g_EL0 [NSRC0 * TREL * HEADS];
__device__ __align__(16) float g_ER0 [NDST0 * TREL * HEADS];
__device__ __align__(16) float g_SKIP0[NDST0 * HID];
__device__ __align__(16) float g_OUT0 [NDST0 * HID];
__device__ __align__(16) float g_H1  [TREL * NDST0 * HID];
__device__ __align__(16) float g_EL1 [NDST0 * TREL * HEADS];
__device__ __align__(16) float g_ER1 [NDST1 * TREL * HEADS];
__device__ __align__(16) float g_SKIP1[NDST1 * HID];
__device__ __align__(16) float g_OUT1 [NDST1 * HID];
__device__ __align__(16) float g_MLPH [NDST1 * HID];

__device__ int g_cnt0 [TREL * NDST0];
__device__ int g_off0 [TREL * (NDST0 + 1)];
__device__ int g_cur0 [TREL * NDST0];
__device__ int g_perm0[TREL * E0];
__device__ int g_cnt1 [TREL * NDST1];
__device__ int g_off1 [TREL * (NDST1 + 1)];
__device__ int g_cur1 [TREL * NDST1];
__device__ int g_perm1[TREL * E1];

__device__ double g_sum[HID];
__device__ double g_sq [HID];

// buffer ids (resolved device-side; avoids any symbol-address work during capture)
enum {
    F_H0 = 0, F_EL0, F_ER0, F_SKIP0, F_OUT0,
    F_H1, F_EL1, F_ER1, F_SKIP1, F_OUT1, F_MLPH
};
enum {
    I_CNT0 = 0, I_OFF0, I_CUR0, I_PERM0,
    I_CNT1, I_OFF1, I_CUR1, I_PERM1
};

__device__ __forceinline__ float* FBUF(int id) {
    switch (id) {
        case F_H0:    return g_H0;
        case F_EL0:   return g_EL0;
        case F_ER0:   return g_ER0;
        case F_SKIP0: return g_SKIP0;
        case F_OUT0:  return g_OUT0;
        case F_H1:    return g_H1;
        case F_EL1:   return g_EL1;
        case F_ER1:   return g_ER1;
        case F_SKIP1: return g_SKIP1;
        case F_OUT1:  return g_OUT1;
        case F_MLPH:  return g_MLPH;
    }
    return nullptr;
}
__device__ __forceinline__ int* IBUF(int id) {
    switch (id) {
        case I_CNT0:  return g_cnt0;
        case I_OFF0:  return g_off0;
        case I_CUR0:  return g_cur0;
        case I_PERM0: return g_perm0;
        case I_CNT1:  return g_cnt1;
        case I_OFF1:  return g_off1;
        case I_CUR1:  return g_cur1;
        case I_PERM1: return g_perm1;
    }
    return nullptr;
}

__device__ __forceinline__ float lrelu(float z) { return z > 0.f ? z : NEG * z; }
__device__ __forceinline__ float wmax(float v) {
    #pragma unroll
    for (int o = 16; o >= 1; o >>= 1) v = fmaxf(v, __shfl_xor_sync(0xffffffffu, v, o));
    return v;
}
__device__ __forceinline__ float wsum(float v) {
    #pragma unroll
    for (int o = 16; o >= 1; o >>= 1) v += __shfl_xor_sync(0xffffffffu, v, o);
    return v;
}

// ---------------- SGEMM: C[M,N] = A[M,K] @ B[K,N] (+bias), batch in z ----------------
__global__ void __launch_bounds__(256)
sgemm_k(const float* __restrict__ Aext, int Aid,
        const float* __restrict__ Bg, const float* __restrict__ bias,
        float* __restrict__ Cext, int Cid,
        int M, int N, int K, int ldb, int ldc,
        long long Abatch, long long Bbatch, long long Cbatch)
{
    const float* A = (Aext ? Aext : FBUF(Aid)) + (size_t)blockIdx.z * Abatch;
    const float* B = Bg + (size_t)blockIdx.z * Bbatch;
    float*       C = (Cext ? Cext : FBUF(Cid)) + (size_t)blockIdx.z * Cbatch;

    __shared__ float As[16][128];
    __shared__ float Bs[16][128];

    int tid  = threadIdx.x;
    int row0 = blockIdx.y * 128;
    int col0 = blockIdx.x * 128;
    int ty = tid >> 4, tx = tid & 15;

    float acc[8][8];
    #pragma unroll
    for (int i = 0; i < 8; i++)
        #pragma unroll
        for (int j = 0; j < 8; j++) acc[i][j] = 0.f;

    for (int kt = 0; kt < K; kt += 16) {
        #pragma unroll
        for (int l = 0; l < 2; l++) {
            int s  = tid + l * 256;           // 512 float4 slots
            int r  = s >> 2;
            int c4 = (s & 3) * 4;
            int rg = row0 + r;
            float4 v = make_float4(0.f, 0.f, 0.f, 0.f);
            if (rg < M) v = *(const float4*)&A[(size_t)rg * K + kt + c4];
            As[c4 + 0][r] = v.x; As[c4 + 1][r] = v.y;
            As[c4 + 2][r] = v.z; As[c4 + 3][r] = v.w;
        }
        #pragma unroll
        for (int l = 0; l < 8; l++) {
            int s  = tid + l * 256;
            int kk = s >> 7, cc = s & 127;
            int cg = col0 + cc;
            Bs[kk][cc] = (cg < N) ? B[(size_t)(kt + kk) * ldb + cg] : 0.f;
        }
        __syncthreads();
        #pragma unroll
        for (int kk = 0; kk < 16; kk++) {
            float a[8], b[8];
            *(float4*)&a[0] = *(const float4*)&As[kk][ty * 8];
            *(float4*)&a[4] = *(const float4*)&As[kk][ty * 8 + 4];
            *(float4*)&b[0] = *(const float4*)&Bs[kk][tx * 8];
            *(float4*)&b[4] = *(const float4*)&Bs[kk][tx * 8 + 4];
            #pragma unroll
            for (int i = 0; i < 8; i++)
                #pragma unroll
                for (int j = 0; j < 8; j++) acc[i][j] += a[i] * b[j];
        }
        __syncthreads();
    }
    #pragma unroll
    for (int i = 0; i < 8; i++) {
        int r = row0 + ty * 8 + i;
        if (r >= M) continue;
        #pragma unroll
        for (int j = 0; j < 8; j++) {
            int c = col0 + tx * 8 + j;
            if (c < N) C[(size_t)r * ldc + c] = acc[i][j] + (bias ? bias[c] : 0.f);
        }
    }
}

// ---------------- el/er from H: one warp per (node, relation) ----------------
__global__ void eler_k(int Hid, const float* __restrict__ al, const float* __restrict__ ar,
                       int ELid, int ERid, int n_src, int n_dst)
{
    const float* Hb = FBUF(Hid);
    float* EL = FBUF(ELid);
    float* ER = FBUF(ERid);
    int w    = (blockIdx.x * blockDim.x + threadIdx.x) >> 5;
    int lane = threadIdx.x & 31;
    int total = n_src * TREL;
    if (w >= total) return;
    int j = w / n_src;
    int i = w - j * n_src;

    float4 hv = *(const float4*)&Hb[((size_t)j * n_src + i) * HID + lane * 4];
    float4 av = *(const float4*)&al[j * HID + lane * 4];
    float pl = hv.x * av.x + hv.y * av.y + hv.z * av.z + hv.w * av.w;
    float pr = 0.f;
    if (i < n_dst) {
        float4 rv = *(const float4*)&ar[j * HID + lane * 4];
        pr = hv.x * rv.x + hv.y * rv.y + hv.z * rv.z + hv.w * rv.w;
    }
    #pragma unroll
    for (int o = 4; o >= 1; o >>= 1) {
        pl += __shfl_down_sync(0xffffffffu, pl, o, 8);
        pr += __shfl_down_sync(0xffffffffu, pr, o, 8);
    }
    if ((lane & 7) == 0) {
        int h = lane >> 3;
        EL[(size_t)i * (TREL * HEADS) + j * HEADS + h] = pl;
        if (i < n_dst) ER[(size_t)i * (TREL * HEADS) + j * HEADS + h] = pr;
    }
}

// ---------------- CSR build (z = relation; no int division in hot loop) ----------------
__global__ void zero_i_k(int id, int n) {
    int* p = IBUF(id);
    for (int i = blockIdx.x * blockDim.x + threadIdx.x; i < n; i += gridDim.x * blockDim.x)
        p[i] = 0;
}

__global__ void count_k(const int* __restrict__ dst, int E, int n_dst, int cntid) {
    int j = blockIdx.z;
    int* cnt = IBUF(cntid) + j * n_dst;
    const int* dj = dst + (size_t)j * E;
    for (int e = blockIdx.x * blockDim.x + threadIdx.x; e < E; e += gridDim.x * blockDim.x)
        atomicAdd(&cnt[dj[e]], 1);
}

__global__ void scan_k(int cntid, int offid, int n) {
    __shared__ int sh[1024];
    const int* cnt = IBUF(cntid) + blockIdx.x * n;
    int* off = IBUF(offid) + blockIdx.x * (n + 1);
    int carry = 0;
    for (int base = 0; base < n; base += 1024) {
        int i = base + threadIdx.x;
        int v = (i < n) ? cnt[i] : 0;
        sh[threadIdx.x] = v;
        __syncthreads();
        for (int o = 1; o < 1024; o <<= 1) {
            int t = (threadIdx.x >= o) ? sh[threadIdx.x - o] : 0;
            __syncthreads();
            sh[threadIdx.x] += t;
            __syncthreads();
        }
        if (i < n) off[i] = carry + sh[threadIdx.x] - v;
        int tot = sh[1023];
        __syncthreads();
        carry += tot;
    }
    if (threadIdx.x == 0) off[n] = carry;
}

__global__ void initcur_k(int offid, int curid, int n) {
    const int* off = IBUF(offid);
    int* cur = IBUF(curid);
    int tot = TREL * n;
    for (int idx = blockIdx.x * blockDim.x + threadIdx.x; idx < tot; idx += gridDim.x * blockDim.x) {
        int j = idx / n, d = idx - j * n;
        cur[idx] = off[j * (n + 1) + d];
    }
}

__global__ void fill_k(const int* __restrict__ dst, int E, int n_dst, int curid, int permid) {
    int j = blockIdx.z;
    int* cur  = IBUF(curid) + j * n_dst;
    int* perm = IBUF(permid) + (size_t)j * E;
    const int* dj = dst + (size_t)j * E;
    for (int e = blockIdx.x * blockDim.x + threadIdx.x; e < E; e += gridDim.x * blockDim.x) {
        int pos = atomicAdd(&cur[dj[e]], 1);
        perm[pos] = e;
    }
}

// ---------------- attention aggregation: one warp per dst, all relations ----------------
__global__ void agg_k(int Hid, int ELid, int ERid, const int* __restrict__ src,
                      int offid, int permid, int SKIPid, const float* __restrict__ b,
                      int OUTid, int n_src, int n_dst, int E)
{
    const float* Hb = FBUF(Hid);
    const float* EL = FBUF(ELid);
    const float* ER = FBUF(ERid);
    const float* SK = FBUF(SKIPid);
    float* OUTp = FBUF(OUTid);
    const int* off  = IBUF(offid);
    const int* perm = IBUF(permid);

    int w    = (blockIdx.x * blockDim.x + threadIdx.x) >> 5;
    int lane = threadIdx.x & 31;
    if (w >= n_dst) return;
    int d = w;
    int h = lane >> 3;

    float4 acc = *(const float4*)&SK[(size_t)d * HID + lane * 4];
    #pragma unroll
    for (int j = 0; j < TREL; j++) {
        float4 bv = *(const float4*)&b[j * HID + lane * 4];
        acc.x += bv.x; acc.y += bv.y; acc.z += bv.z; acc.w += bv.w;
    }

    for (int j = 0; j < TREL; j++) {
        int s0 = off[j * (n_dst + 1) + d];
        int s1 = off[j * (n_dst + 1) + d + 1];
        if (s1 == s0) continue;
        float4 er4 = *(const float4*)&ER[(size_t)d * (TREL * HEADS) + j * HEADS];
        const int* pj = perm + (size_t)j * E;
        const int* sj = src  + (size_t)j * E;

        // pass 1: per-head max
        float m0 = -3.4e38f, m1 = m0, m2 = m0, m3 = m0;
        for (int p = s0 + lane; p < s1; p += 32) {
            int s = sj[pj[p]];
            float4 el4 = *(const float4*)&EL[(size_t)s * (TREL * HEADS) + j * HEADS];
            m0 = fmaxf(m0, lrelu(el4.x + er4.x));
            m1 = fmaxf(m1, lrelu(el4.y + er4.y));
            m2 = fmaxf(m2, lrelu(el4.z + er4.z));
            m3 = fmaxf(m3, lrelu(el4.w + er4.w));
        }
        m0 = wmax(m0); m1 = wmax(m1); m2 = wmax(m2); m3 = wmax(m3);

        // pass 2: per-head sum of exp
        float z0 = 0.f, z1 = 0.f, z2 = 0.f, z3 = 0.f;
        for (int p = s0 + lane; p < s1; p += 32) {
            int s = sj[pj[p]];
            float4 el4 = *(const float4*)&EL[(size_t)s * (TREL * HEADS) + j * HEADS];
            z0 += __expf(lrelu(el4.x + er4.x) - m0);
            z1 += __expf(lrelu(el4.y + er4.y) - m1);
            z2 += __expf(lrelu(el4.z + er4.z) - m2);
            z3 += __expf(lrelu(el4.w + er4.w) - m3);
        }
        z0 = wsum(z0); z1 = wsum(z1); z2 = wsum(z2); z3 = wsum(z3);
        float i0 = 1.f / (z0 + 1e-16f), i1 = 1.f / (z1 + 1e-16f);
        float i2 = 1.f / (z2 + 1e-16f), i3 = 1.f / (z3 + 1e-16f);

        float mh   = (h == 0) ? m0 : (h == 1) ? m1 : (h == 2) ? m2 : m3;
        float invh = (h == 0) ? i0 : (h == 1) ? i1 : (h == 2) ? i2 : i3;
        float erh  = (h == 0) ? er4.x : (h == 1) ? er4.y : (h == 2) ? er4.z : er4.w;

        // pass 3: weighted gather (whole warp per edge, coalesced 512B rows)
        for (int p = s0; p < s1; p++) {
            int e = pj[p];
            int s = sj[e];
            float elh = EL[(size_t)s * (TREL * HEADS) + j * HEADS + h];
            float wgt = __expf(lrelu(elh + erh) - mh) * invh;
            float4 hv = *(const float4*)&Hb[((size_t)j * n_src + s) * HID + lane * 4];
            acc.x += wgt * hv.x; acc.y += wgt * hv.y;
            acc.z += wgt * hv.z; acc.w += wgt * hv.w;
        }
    }
    *(float4*)&OUTp[(size_t)d * HID + lane * 4] = acc;
}

// ---------------- column (axis-0) statistics + normalize + activation ----------------
__global__ void zstat_k() {
    int t = threadIdx.x;
    if (t < HID) { g_sum[t] = 0.0; g_sq[t] = 0.0; }
}

__global__ void colstat_k(int Xid, int n) {
    const float* X = FBUF(Xid);
    int c = threadIdx.x;   // 128 threads
    float s = 0.f, q = 0.f;
    for (int r = blockIdx.x * 2; r < n; r += gridDim.x * 2) {
        float v = X[(size_t)r * HID + c];
        s += v; q += v * v;
        int r2 = r + 1;
        if (r2 < n) {
            float v2 = X[(size_t)r2 * HID + c];
            s += v2; q += v2 * v2;
        }
    }
    atomicAdd(&g_sum[c], (double)s);
    atomicAdd(&g_sq [c], (double)q);
}

// act: 0 = elu, 1 = relu
__global__ void norm_k(int Xid, int Yid, const float* __restrict__ g,
                       const float* __restrict__ be, int n, int act)
{
    const float* X = FBUF(Xid);
    float* Y = FBUF(Yid);
    int c = threadIdx.x;
    double mean = g_sum[c] / (double)n;
    double var  = g_sq[c] / (double)n - mean * mean;
    float fm = (float)mean;
    float sc = (float)(1.0 / sqrt(var + EPSV));
    float gg = g[c] * sc;
    float bb = be[c];
    for (int r = blockIdx.x; r < n; r += gridDim.x) {
        float v = (X[(size_t)r * HID + c] - fm) * gg + bb;
        float y;
        if (act == 0) y = v > 0.f ? v : expm1f(v);
        else          y = v > 0.f ? v : 0.f;
        Y[(size_t)r * HID + c] = y;
    }
}

static inline int cdiv(int a, int b) { return (a + b - 1) / b; }

// ---------------- launcher ----------------
extern "C" void kernel_launch(void* const* d_in, const int* in_sizes, int n_in,
                              void* d_out, int out_size)
{
    const float* x    = (const float*)d_in[0];
    const float* W0   = (const float*)d_in[1];
    const float* al0  = (const float*)d_in[2];
    const float* ar0  = (const float*)d_in[3];
    const float* b0   = (const float*)d_in[4];
    const float* Ws0  = (const float*)d_in[5];
    const float* bs0  = (const float*)d_in[6];
    const float* g0   = (const float*)d_in[7];
    const float* be0  = (const float*)d_in[8];
    const float* W1   = (const float*)d_in[9];
    const float* al1  = (const float*)d_in[10];
    const float* ar1  = (const float*)d_in[11];
    const float* b1   = (const float*)d_in[12];
    const float* Ws1  = (const float*)d_in[13];
    const float* bs1  = (const float*)d_in[14];
    const float* g1   = (const float*)d_in[15];
    const float* be1  = (const float*)d_in[16];
    const float* Wm1  = (const float*)d_in[17];
    const float* bm1  = (const float*)d_in[18];
    const float* gm   = (const float*)d_in[19];
    const float* bem  = (const float*)d_in[20];
    const float* Wm2  = (const float*)d_in[21];
    const float* bm2  = (const float*)d_in[22];
    const int*   src0 = (const int*)d_in[23];
    const int*   dst0 = (const int*)d_in[24];
    const int*   src1 = (const int*)d_in[25];
    const int*   dst1 = (const int*)d_in[26];
    float* out = (float*)d_out;

    // ===== Layer 0 =====
    sgemm_k<<<dim3(1, cdiv(NSRC0, 128), TREL), 256>>>(
        x, -1, W0, nullptr, nullptr, F_H0,
        NSRC0, HID, INFEAT, HID, HID,
        0LL, (long long)INFEAT * HID, (long long)NSRC0 * HID);
    sgemm_k<<<dim3(1, cdiv(NDST0, 128), 1), 256>>>(
        x, -1, Ws0, bs0, nullptr, F_SKIP0,
        NDST0, HID, INFEAT, HID, HID, 0LL, 0LL, 0LL);
    eler_k<<<cdiv(NSRC0 * TREL * 32, 256), 256>>>(F_H0, al0, ar0, F_EL0, F_ER0, NSRC0, NDST0);
    zero_i_k<<<256, 256>>>(I_CNT0, TREL * NDST0);
    count_k<<<dim3(1024, 1, TREL), 256>>>(dst0, E0, NDST0, I_CNT0);
    scan_k<<<TREL, 1024>>>(I_CNT0, I_OFF0, NDST0);
    initcur_k<<<256, 256>>>(I_OFF0, I_CUR0, NDST0);
    fill_k<<<dim3(1024, 1, TREL), 256>>>(dst0, E0, NDST0, I_CUR0, I_PERM0);
    agg_k<<<cdiv(NDST0 * 32, 256), 256>>>(F_H0, F_EL0, F_ER0, src0, I_OFF0, I_PERM0,
                                          F_SKIP0, b0, F_OUT0, NSRC0, NDST0, E0);
    zstat_k<<<1, 128>>>();
    colstat_k<<<256, 128>>>(F_OUT0, NDST0);
    norm_k<<<256, 128>>>(F_OUT0, F_OUT0, g0, be0, NDST0, 0);

    // ===== Layer 1 =====
    sgemm_k<<<dim3(1, cdiv(NDST0, 128), TREL), 256>>>(
        nullptr, F_OUT0, W1, nullptr, nullptr, F_H1,
        NDST0, HID, HID, HID, HID,
        0LL, (long long)HID * HID, (long long)NDST0 * HID);
    sgemm_k<<<dim3(1, cdiv(NDST1, 128), 1), 256>>>(
        nullptr, F_OUT0, Ws1, bs1, nullptr, F_SKIP1,
        NDST1, HID, HID, HID, HID, 0LL, 0LL, 0LL);
    eler_k<<<cdiv(NDST0 * TREL * 32, 256), 256>>>(F_H1, al1, ar1, F_EL1, F_ER1, NDST0, NDST1);
    zero_i_k<<<256, 256>>>(I_CNT1, TREL * NDST1);
    count_k<<<dim3(512, 1, TREL), 256>>>(dst1, E1, NDST1, I_CNT1);
    scan_k<<<TREL, 1024>>>(I_CNT1, I_OFF1, NDST1);
    initcur_k<<<256, 256>>>(I_OFF1, I_CUR1, NDST1);
    fill_k<<<dim3(512, 1, TREL), 256>>>(dst1, E1, NDST1, I_CUR1, I_PERM1);
    agg_k<<<cdiv(NDST1 * 32, 256), 256>>>(F_H1, F_EL1, F_ER1, src1, I_OFF1, I_PERM1,
                                          F_SKIP1, b1, F_OUT1, NDST0, NDST1, E1);
    zstat_k<<<1, 128>>>();
    colstat_k<<<256, 128>>>(F_OUT1, NDST1);
    norm_k<<<256, 128>>>(F_OUT1, F_OUT1, g1, be1, NDST1, 0);

    // ===== MLP =====
    sgemm_k<<<dim3(1, cdiv(NDST1, 128), 1), 256>>>(
        nullptr, F_OUT1, Wm1, bm1, nullptr, F_MLPH,
        NDST1, HID, HID, HID, HID, 0LL, 0LL, 0LL);
    zstat_k<<<1, 128>>>();
    colstat_k<<<256, 128>>>(F_MLPH, NDST1);
    norm_k<<<256, 128>>>(F_MLPH, F_MLPH, gm, bem, NDST1, 1);
    sgemm_k<<<dim3(cdiv(OUTF, 128), cdiv(NDST1, 128), 1), 256>>>(
        nullptr, F_MLPH, Wm2, bm2, out, -1,
        NDST1, OUTF, HID, OUTF, OUTF, 0LL, 0LL, 0LL);
}

// round 3
// speedup vs baseline: 1.2436x; 1.2436x over previous
#include <cuda_runtime.h>
#include <math.h>
#include <stdint.h>

// ---------------- problem constants ----------------
#define TREL   5
#define HEADS  4
#define HID    128
#define INFEAT 256
#define OUTF   153
#define NSRC0  120000
#define NDST0  40000
#define NDST1  10000
#define E0     800000
#define E1     300000
#define NEG    0.2f
#define EPSV   1e-5

// ---------------- device scratch (static, allowed) ----------------
__device__ __align__(16) float g_H0  [TREL * NSRC0 * HID];
__device__ __align__(16) float g_EL0 [NSRC0 * TREL * HEADS];
__device__ __align__(16) float g_ER0 [NDST0 * TREL * HEADS];
__device__ __align__(16) float g_SKIP0[NDST0 * HID];
__device__ __align__(16) float g_OUT0 [NDST0 * HID];
__device__ __align__(16) float g_H1  [TREL * NDST0 * HID];
__device__ __align__(16) float g_EL1 [NDST0 * TREL * HEADS];
__device__ __align__(16) float g_ER1 [NDST1 * TREL * HEADS];
__device__ __align__(16) float g_SKIP1[NDST1 * HID];
__device__ __align__(16) float g_OUT1 [NDST1 * HID];
__device__ __align__(16) float g_MLPH [NDST1 * HID];

__device__ int g_cnt0 [TREL * NDST0];
__device__ int g_off0 [TREL * (NDST0 + 1)];
__device__ int g_cur0 [TREL * NDST0];
__device__ int g_perm0[TREL * E0];
__device__ int g_cnt1 [TREL * NDST1];
__device__ int g_off1 [TREL * (NDST1 + 1)];
__device__ int g_cur1 [TREL * NDST1];
__device__ int g_perm1[TREL * E1];

__device__ double g_sum[HID];
__device__ double g_sq [HID];

enum {
    F_H0 = 0, F_EL0, F_ER0, F_SKIP0, F_OUT0,
    F_H1, F_EL1, F_ER1, F_SKIP1, F_OUT1, F_MLPH
};
enum {
    I_CNT0 = 0, I_OFF0, I_CUR0, I_PERM0,
    I_CNT1, I_OFF1, I_CUR1, I_PERM1
};

__device__ __forceinline__ float* FBUF(int id) {
    switch (id) {
        case F_H0:    return g_H0;
        case F_EL0:   return g_EL0;
        case F_ER0:   return g_ER0;
        case F_SKIP0: return g_SKIP0;
        case F_OUT0:  return g_OUT0;
        case F_H1:    return g_H1;
        case F_EL1:   return g_EL1;
        case F_ER1:   return g_ER1;
        case F_SKIP1: return g_SKIP1;
        case F_OUT1:  return g_OUT1;
        case F_MLPH:  return g_MLPH;
    }
    return nullptr;
}
__device__ __forceinline__ int* IBUF(int id) {
    switch (id) {
        case I_CNT0:  return g_cnt0;
        case I_OFF0:  return g_off0;
        case I_CUR0:  return g_cur0;
        case I_PERM0: return g_perm0;
        case I_CNT1:  return g_cnt1;
        case I_OFF1:  return g_off1;
        case I_CUR1:  return g_cur1;
        case I_PERM1: return g_perm1;
    }
    return nullptr;
}

__device__ __forceinline__ float lrelu(float z) { return z > 0.f ? z : NEG * z; }

// ---------------- tf32 helpers ----------------
__device__ __forceinline__ uint32_t f2tf(float x) {
    uint32_t r;
    asm("cvt.rna.tf32.f32 %0, %1;" : "=r"(r) : "f"(x));
    return r;
}
__device__ __forceinline__ void tf_split(float x, uint32_t& hi, uint32_t& lo) {
    hi = f2tf(x);
    lo = f2tf(x - __uint_as_float(hi));
}
__device__ __forceinline__ void mma_tf32(float* d, const uint32_t* a, const uint32_t* b) {
    asm volatile(
        "mma.sync.aligned.m16n8k8.row.col.f32.tf32.tf32.f32 "
        "{%0,%1,%2,%3}, {%4,%5,%6,%7}, {%8,%9}, {%0,%1,%2,%3};"
        : "+f"(d[0]), "+f"(d[1]), "+f"(d[2]), "+f"(d[3])
        : "r"(a[0]), "r"(a[1]), "r"(a[2]), "r"(a[3]), "r"(b[0]), "r"(b[1]));
}

// ---------------- tensor-core GEMM: C[M,128] = A[M,K] @ B[K,128] (+bias) ----------------
// 3xTF32 split -> ~fp32 accuracy. N fixed at 128. K multiple of 32. Batch in z.
#define APAD 36
#define BPAD 136
__global__ void __launch_bounds__(256)
mma_gemm_k(const float* __restrict__ Aext, int Aid,
           const float* __restrict__ Bg, const float* __restrict__ bias,
           float* __restrict__ Cext, int Cid,
           int M, int K,
           long long Abatch, long long Bbatch, long long Cbatch)
{
    const float* A = (Aext ? Aext : FBUF(Aid)) + (size_t)blockIdx.z * Abatch;
    const float* B = Bg + (size_t)blockIdx.z * Bbatch;
    float*       C = (Cext ? Cext : FBUF(Cid)) + (size_t)blockIdx.z * Cbatch;

    __shared__ float As[128 * APAD];
    __shared__ float Bs[32 * BPAD];

    int tid  = threadIdx.x;
    int warp = tid >> 5, lane = tid & 31;
    int g = lane >> 2, t4 = lane & 3;
    int wr = (warp & 3) * 32;     // warp row within 128
    int wc = (warp >> 2) * 64;    // warp col within 128
    int row0 = blockIdx.y * 128;

    float acc[2][8][4];
    #pragma unroll
    for (int mi = 0; mi < 2; mi++)
        #pragma unroll
        for (int ni = 0; ni < 8; ni++)
            #pragma unroll
            for (int q = 0; q < 4; q++) acc[mi][ni][q] = 0.f;

    for (int kt = 0; kt < K; kt += 32) {
        // stage A: 128 x 32
        #pragma unroll
        for (int l = 0; l < 4; l++) {
            int s  = tid + l * 256;          // 1024 float4 slots
            int r  = s >> 3;
            int c4 = (s & 7) * 4;
            int rg = row0 + r;
            float4 v = make_float4(0.f, 0.f, 0.f, 0.f);
            if (rg < M) v = *(const float4*)&A[(size_t)rg * K + kt + c4];
            As[r * APAD + c4 + 0] = v.x;
            As[r * APAD + c4 + 1] = v.y;
            As[r * APAD + c4 + 2] = v.z;
            As[r * APAD + c4 + 3] = v.w;
        }
        // stage B: 32 x 128 (BPAD multiple of 4 -> float4 stores aligned)
        #pragma unroll
        for (int l = 0; l < 4; l++) {
            int s  = tid + l * 256;
            int r  = s >> 5;
            int c4 = (s & 31) * 4;
            float4 v = *(const float4*)&B[(size_t)(kt + r) * 128 + c4];
            *(float4*)&Bs[r * BPAD + c4] = v;
        }
        __syncthreads();

        #pragma unroll
        for (int k8 = 0; k8 < 4; k8++) {
            int kb = k8 * 8;
            // A fragments (hi/lo) for 2 M-atoms
            uint32_t ah[2][4], al[2][4];
            #pragma unroll
            for (int mi = 0; mi < 2; mi++) {
                int r0 = wr + mi * 16 + g;
                float v0 = As[(r0    ) * APAD + kb + t4    ];
                float v1 = As[(r0 + 8) * APAD + kb + t4    ];
                float v2 = As[(r0    ) * APAD + kb + t4 + 4];
                float v3 = As[(r0 + 8) * APAD + kb + t4 + 4];
                tf_split(v0, ah[mi][0], al[mi][0]);
                tf_split(v1, ah[mi][1], al[mi][1]);
                tf_split(v2, ah[mi][2], al[mi][2]);
                tf_split(v3, ah[mi][3], al[mi][3]);
            }
            #pragma unroll
            for (int ni = 0; ni < 8; ni++) {
                int c0 = wc + ni * 8 + g;
                float b0 = Bs[(kb + t4    ) * BPAD + c0];
                float b1 = Bs[(kb + t4 + 4) * BPAD + c0];
                uint32_t bh[2], bl[2];
                tf_split(b0, bh[0], bl[0]);
                tf_split(b1, bh[1], bl[1]);
                #pragma unroll
                for (int mi = 0; mi < 2; mi++) {
                    mma_tf32(acc[mi][ni], ah[mi], bh);   // hi*hi
                    mma_tf32(acc[mi][ni], al[mi], bh);   // lo*hi
                    mma_tf32(acc[mi][ni], ah[mi], bl);   // hi*lo
                }
            }
        }
        __syncthreads();
    }

    // epilogue
    #pragma unroll
    for (int mi = 0; mi < 2; mi++) {
        int r0 = row0 + wr + mi * 16 + g;
        #pragma unroll
        for (int ni = 0; ni < 8; ni++) {
            int c0 = wc + ni * 8 + t4 * 2;
            float bz0 = bias ? bias[c0] : 0.f;
            float bz1 = bias ? bias[c0 + 1] : 0.f;
            if (r0 < M) {
                float2 v = make_float2(acc[mi][ni][0] + bz0, acc[mi][ni][1] + bz1);
                *(float2*)&C[(size_t)r0 * 128 + c0] = v;
            }
            if (r0 + 8 < M) {
                float2 v = make_float2(acc[mi][ni][2] + bz0, acc[mi][ni][3] + bz1);
                *(float2*)&C[(size_t)(r0 + 8) * 128 + c0] = v;
            }
        }
    }
}

// ---------------- fallback FFMA SGEMM (final OUT gemm, N=153) ----------------
__global__ void __launch_bounds__(256)
sgemm_k(const float* __restrict__ Aext, int Aid,
        const float* __restrict__ Bg, const float* __restrict__ bias,
        float* __restrict__ Cext, int Cid,
        int M, int N, int K, int ldb, int ldc)
{
    const float* A = (Aext ? Aext : FBUF(Aid));
    const float* B = Bg;
    float*       C = (Cext ? Cext : FBUF(Cid));

    __shared__ float As[16][128];
    __shared__ float Bs[16][128];

    int tid  = threadIdx.x;
    int row0 = blockIdx.y * 128;
    int col0 = blockIdx.x * 128;
    int ty = tid >> 4, tx = tid & 15;

    float acc[8][8];
    #pragma unroll
    for (int i = 0; i < 8; i++)
        #pragma unroll
        for (int j = 0; j < 8; j++) acc[i][j] = 0.f;

    for (int kt = 0; kt < K; kt += 16) {
        #pragma unroll
        for (int l = 0; l < 2; l++) {
            int s  = tid + l * 256;
            int r  = s >> 2;
            int c4 = (s & 3) * 4;
            int rg = row0 + r;
            float4 v = make_float4(0.f, 0.f, 0.f, 0.f);
            if (rg < M) v = *(const float4*)&A[(size_t)rg * K + kt + c4];
            As[c4 + 0][r] = v.x; As[c4 + 1][r] = v.y;
            As[c4 + 2][r] = v.z; As[c4 + 3][r] = v.w;
        }
        #pragma unroll
        for (int l = 0; l < 8; l++) {
            int s  = tid + l * 256;
            int kk = s >> 7, cc = s & 127;
            int cg = col0 + cc;
            Bs[kk][cc] = (cg < N) ? B[(size_t)(kt + kk) * ldb + cg] : 0.f;
        }
        __syncthreads();
        #pragma unroll
        for (int kk = 0; kk < 16; kk++) {
            float a[8], b[8];
            *(float4*)&a[0] = *(const float4*)&As[kk][ty * 8];
            *(float4*)&a[4] = *(const float4*)&As[kk][ty * 8 + 4];
            *(float4*)&b[0] = *(const float4*)&Bs[kk][tx * 8];
            *(float4*)&b[4] = *(const float4*)&Bs[kk][tx * 8 + 4];
            #pragma unroll
            for (int i = 0; i < 8; i++)
                #pragma unroll
                for (int j = 0; j < 8; j++) acc[i][j] += a[i] * b[j];
        }
        __syncthreads();
    }
    #pragma unroll
    for (int i = 0; i < 8; i++) {
        int r = row0 + ty * 8 + i;
        if (r >= M) continue;
        #pragma unroll
        for (int j = 0; j < 8; j++) {
            int c = col0 + tx * 8 + j;
            if (c < N) C[(size_t)r * ldc + c] = acc[i][j] + (bias ? bias[c] : 0.f);
        }
    }
}

// ---------------- el/er from H: one warp per (node, relation) ----------------
__global__ void eler_k(int Hid, const float* __restrict__ al, const float* __restrict__ ar,
                       int ELid, int ERid, int n_src, int n_dst)
{
    const float* Hb = FBUF(Hid);
    float* EL = FBUF(ELid);
    float* ER = FBUF(ERid);
    int w    = (blockIdx.x * blockDim.x + threadIdx.x) >> 5;
    int lane = threadIdx.x & 31;
    int total = n_src * TREL;
    if (w >= total) return;
    int j = w / n_src;
    int i = w - j * n_src;

    float4 hv = *(const float4*)&Hb[((size_t)j * n_src + i) * HID + lane * 4];
    float4 av = *(const float4*)&al[j * HID + lane * 4];
    float pl = hv.x * av.x + hv.y * av.y + hv.z * av.z + hv.w * av.w;
    float pr = 0.f;
    if (i < n_dst) {
        float4 rv = *(const float4*)&ar[j * HID + lane * 4];
        pr = hv.x * rv.x + hv.y * rv.y + hv.z * rv.z + hv.w * rv.w;
    }
    #pragma unroll
    for (int o = 4; o >= 1; o >>= 1) {
        pl += __shfl_down_sync(0xffffffffu, pl, o, 8);
        pr += __shfl_down_sync(0xffffffffu, pr, o, 8);
    }
    if ((lane & 7) == 0) {
        int h = lane >> 3;
        EL[(size_t)i * (TREL * HEADS) + j * HEADS + h] = pl;
        if (i < n_dst) ER[(size_t)i * (TREL * HEADS) + j * HEADS + h] = pr;
    }
}

// ---------------- CSR build ----------------
__global__ void zero_i_k(int id, int n) {
    int* p = IBUF(id);
    for (int i = blockIdx.x * blockDim.x + threadIdx.x; i < n; i += gridDim.x * blockDim.x)
        p[i] = 0;
}

__global__ void count_k(const int* __restrict__ dst, int E, int n_dst, int cntid) {
    int j = blockIdx.z;
    int* cnt = IBUF(cntid) + j * n_dst;
    const int* dj = dst + (size_t)j * E;
    for (int e = blockIdx.x * blockDim.x + threadIdx.x; e < E; e += gridDim.x * blockDim.x)
        atomicAdd(&cnt[dj[e]], 1);
}

__global__ void scan_k(int cntid, int offid, int n) {
    __shared__ int sh[1024];
    const int* cnt = IBUF(cntid) + blockIdx.x * n;
    int* off = IBUF(offid) + blockIdx.x * (n + 1);
    int carry = 0;
    for (int base = 0; base < n; base += 1024) {
        int i = base + threadIdx.x;
        int v = (i < n) ? cnt[i] : 0;
        sh[threadIdx.x] = v;
        __syncthreads();
        for (int o = 1; o < 1024; o <<= 1) {
            int t = (threadIdx.x >= o) ? sh[threadIdx.x - o] : 0;
            __syncthreads();
            sh[threadIdx.x] += t;
            __syncthreads();
        }
        if (i < n) off[i] = carry + sh[threadIdx.x] - v;
        int tot = sh[1023];
        __syncthreads();
        carry += tot;
    }
    if (threadIdx.x == 0) off[n] = carry;
}

__global__ void initcur_k(int offid, int curid, int n) {
    const int* off = IBUF(offid);
    int* cur = IBUF(curid);
    int tot = TREL * n;
    for (int idx = blockIdx.x * blockDim.x + threadIdx.x; idx < tot; idx += gridDim.x * blockDim.x) {
        int j = idx / n, d = idx - j * n;
        cur[idx] = off[j * (n + 1) + d];
    }
}

// perm stores the SRC NODE id directly (removes one random hop in agg)
__global__ void fill_k(const int* __restrict__ dst, const int* __restrict__ src,
                       int E, int n_dst, int curid, int permid) {
    int j = blockIdx.z;
    int* cur  = IBUF(curid) + j * n_dst;
    int* perm = IBUF(permid) + (size_t)j * E;
    const int* dj = dst + (size_t)j * E;
    const int* sj = src + (size_t)j * E;
    for (int e = blockIdx.x * blockDim.x + threadIdx.x; e < E; e += gridDim.x * blockDim.x) {
        int pos = atomicAdd(&cur[dj[e]], 1);
        perm[pos] = sj[e];
    }
}

// ---------------- attention aggregation: single pass, one warp per dst ----------------
__global__ void agg_k(int Hid, int ELid, int ERid,
                      int offid, int permid, int SKIPid, const float* __restrict__ b,
                      int OUTid, int n_src, int n_dst, int E)
{
    const float* Hb = FBUF(Hid);
    const float* EL = FBUF(ELid);
    const float* ER = FBUF(ERid);
    const float* SK = FBUF(SKIPid);
    float* OUTp = FBUF(OUTid);
    const int* off  = IBUF(offid);
    const int* perm = IBUF(permid);

    int w    = (blockIdx.x * blockDim.x + threadIdx.x) >> 5;
    int lane = threadIdx.x & 31;
    if (w >= n_dst) return;
    int d = w;
    int h = lane >> 3;

    float4 acc = *(const float4*)&SK[(size_t)d * HID + lane * 4];
    #pragma unroll
    for (int j = 0; j < TREL; j++) {
        float4 bv = *(const float4*)&b[j * HID + lane * 4];
        acc.x += bv.x; acc.y += bv.y; acc.z += bv.z; acc.w += bv.w;
    }

    for (int j = 0; j < TREL; j++) {
        int s0 = off[j * (n_dst + 1) + d];
        int s1 = off[j * (n_dst + 1) + d + 1];
        if (s1 == s0) continue;
        float erh = ER[(size_t)d * (TREL * HEADS) + j * HEADS + h];
        const int* pj = perm + (size_t)j * E;
        const float* Hj = Hb + (size_t)j * n_src * HID;

        float4 racc = make_float4(0.f, 0.f, 0.f, 0.f);
        float z = 0.f;
        int p = s0;
        for (; p + 1 < s1; p += 2) {
            int sA = pj[p];
            int sB = pj[p + 1];
            float eA = EL[(size_t)sA * (TREL * HEADS) + j * HEADS + h];
            float eB = EL[(size_t)sB * (TREL * HEADS) + j * HEADS + h];
            float4 hA = *(const float4*)&Hj[(size_t)sA * HID + lane * 4];
            float4 hB = *(const float4*)&Hj[(size_t)sB * HID + lane * 4];
            float wA = __expf(fminf(lrelu(eA + erh), 80.f));
            float wB = __expf(fminf(lrelu(eB + erh), 80.f));
            z += wA + wB;
            racc.x += wA * hA.x + wB * hB.x;
            racc.y += wA * hA.y + wB * hB.y;
            racc.z += wA * hA.z + wB * hB.z;
            racc.w += wA * hA.w + wB * hB.w;
        }
        if (p < s1) {
            int sA = pj[p];
            float eA = EL[(size_t)sA * (TREL * HEADS) + j * HEADS + h];
            float4 hA = *(const float4*)&Hj[(size_t)sA * HID + lane * 4];
            float wA = __expf(fminf(lrelu(eA + erh), 80.f));
            z += wA;
            racc.x += wA * hA.x; racc.y += wA * hA.y;
            racc.z += wA * hA.z; racc.w += wA * hA.w;
        }
        float inv = 1.f / (z + 1e-16f);
        acc.x += racc.x * inv; acc.y += racc.y * inv;
        acc.z += racc.z * inv; acc.w += racc.w * inv;
    }
    *(float4*)&OUTp[(size_t)d * HID + lane * 4] = acc;
}

// ---------------- column statistics + normalize + activation ----------------
__global__ void zstat_k() {
    int t = threadIdx.x;
    if (t < HID) { g_sum[t] = 0.0; g_sq[t] = 0.0; }
}

__global__ void colstat_k(int Xid, int n) {
    const float* X = FBUF(Xid);
    int c = threadIdx.x;
    float s = 0.f, q = 0.f;
    for (int r = blockIdx.x * 2; r < n; r += gridDim.x * 2) {
        float v = X[(size_t)r * HID + c];
        s += v; q += v * v;
        int r2 = r + 1;
        if (r2 < n) {
            float v2 = X[(size_t)r2 * HID + c];
            s += v2; q += v2 * v2;
        }
    }
    atomicAdd(&g_sum[c], (double)s);
    atomicAdd(&g_sq [c], (double)q);
}

// act: 0 = elu, 1 = relu
__global__ void norm_k(int Xid, int Yid, const float* __restrict__ g,
                       const float* __restrict__ be, int n, int act)
{
    const float* X = FBUF(Xid);
    float* Y = FBUF(Yid);
    int c = threadIdx.x;
    double mean = g_sum[c] / (double)n;
    double var  = g_sq[c] / (double)n - mean * mean;
    float fm = (float)mean;
    float sc = (float)(1.0 / sqrt(var + EPSV));
    float gg = g[c] * sc;
    float bb = be[c];
    for (int r = blockIdx.x; r < n; r += gridDim.x) {
        float v = (X[(size_t)r * HID + c] - fm) * gg + bb;
        float y;
        if (act == 0) y = v > 0.f ? v : expm1f(v);
        else          y = v > 0.f ? v : 0.f;
        Y[(size_t)r * HID + c] = y;
    }
}

static inline int cdiv(int a, int b) { return (a + b - 1) / b; }

// ---------------- launcher ----------------
extern "C" void kernel_launch(void* const* d_in, const int* in_sizes, int n_in,
                              void* d_out, int out_size)
{
    const float* x    = (const float*)d_in[0];
    const float* W0   = (const float*)d_in[1];
    const float* al0  = (const float*)d_in[2];
    const float* ar0  = (const float*)d_in[3];
    const float* b0   = (const float*)d_in[4];
    const float* Ws0  = (const float*)d_in[5];
    const float* bs0  = (const float*)d_in[6];
    const float* g0   = (const float*)d_in[7];
    const float* be0  = (const float*)d_in[8];
    const float* W1   = (const float*)d_in[9];
    const float* al1  = (const float*)d_in[10];
    const float* ar1  = (const float*)d_in[11];
    const float* b1   = (const float*)d_in[12];
    const float* Ws1  = (const float*)d_in[13];
    const float* bs1  = (const float*)d_in[14];
    const float* g1   = (const float*)d_in[15];
    const float* be1  = (const float*)d_in[16];
    const float* Wm1  = (const float*)d_in[17];
    const float* bm1  = (const float*)d_in[18];
    const float* gm   = (const float*)d_in[19];
    const float* bem  = (const float*)d_in[20];
    const float* Wm2  = (const float*)d_in[21];
    const float* bm2  = (const float*)d_in[22];
    const int*   src0 = (const int*)d_in[23];
    const int*   dst0 = (const int*)d_in[24];
    const int*   src1 = (const int*)d_in[25];
    const int*   dst1 = (const int*)d_in[26];
    float* out = (float*)d_out;

    // ===== Layer 0 =====
    mma_gemm_k<<<dim3(1, cdiv(NSRC0, 128), TREL), 256>>>(
        x, -1, W0, nullptr, nullptr, F_H0,
        NSRC0, INFEAT, 0LL, (long long)INFEAT * HID, (long long)NSRC0 * HID);
    mma_gemm_k<<<dim3(1, cdiv(NDST0, 128), 1), 256>>>(
        x, -1, Ws0, bs0, nullptr, F_SKIP0,
        NDST0, INFEAT, 0LL, 0LL, 0LL);
    eler_k<<<cdiv(NSRC0 * TREL * 32, 256), 256>>>(F_H0, al0, ar0, F_EL0, F_ER0, NSRC0, NDST0);
    zero_i_k<<<256, 256>>>(I_CNT0, TREL * NDST0);
    count_k<<<dim3(1024, 1, TREL), 256>>>(dst0, E0, NDST0, I_CNT0);
    scan_k<<<TREL, 1024>>>(I_CNT0, I_OFF0, NDST0);
    initcur_k<<<256, 256>>>(I_OFF0, I_CUR0, NDST0);
    fill_k<<<dim3(1024, 1, TREL), 256>>>(dst0, src0, E0, NDST0, I_CUR0, I_PERM0);
    agg_k<<<cdiv(NDST0 * 32, 256), 256>>>(F_H0, F_EL0, F_ER0, I_OFF0, I_PERM0,
                                          F_SKIP0, b0, F_OUT0, NSRC0, NDST0, E0);
    zstat_k<<<1, 128>>>();
    colstat_k<<<256, 128>>>(F_OUT0, NDST0);
    norm_k<<<256, 128>>>(F_OUT0, F_OUT0, g0, be0, NDST0, 0);

    // ===== Layer 1 =====
    mma_gemm_k<<<dim3(1, cdiv(NDST0, 128), TREL), 256>>>(
        nullptr, F_OUT0, W1, nullptr, nullptr, F_H1,
        NDST0, HID, 0LL, (long long)HID * HID, (long long)NDST0 * HID);
    mma_gemm_k<<<dim3(1, cdiv(NDST1, 128), 1), 256>>>(
        nullptr, F_OUT0, Ws1, bs1, nullptr, F_SKIP1,
        NDST1, HID, 0LL, 0LL, 0LL);
    eler_k<<<cdiv(NDST0 * TREL * 32, 256), 256>>>(F_H1, al1, ar1, F_EL1, F_ER1, NDST0, NDST1);
    zero_i_k<<<256, 256>>>(I_CNT1, TREL * NDST1);
    count_k<<<dim3(512, 1, TREL), 256>>>(dst1, E1, NDST1, I_CNT1);
    scan_k<<<TREL, 1024>>>(I_CNT1, I_OFF1, NDST1);
    initcur_k<<<256, 256>>>(I_OFF1, I_CUR1, NDST1);
    fill_k<<<dim3(512, 1, TREL), 256>>>(dst1, src1, E1, NDST1, I_CUR1, I_PERM1);
    agg_k<<<cdiv(NDST1 * 32, 256), 256>>>(F_H1, F_EL1, F_ER1, I_OFF1, I_PERM1,
                                          F_SKIP1, b1, F_OUT1, NDST0, NDST1, E1);
    zstat_k<<<1, 128>>>();
    colstat_k<<<256, 128>>>(F_OUT1, NDST1);
    norm_k<<<256, 128>>>(F_OUT1, F_OUT1, g1, be1, NDST1, 0);

    // ===== MLP =====
    mma_gemm_k<<<dim3(1, cdiv(NDST1, 128), 1), 256>>>(
        nullptr, F_OUT1, Wm1, bm1, nullptr, F_MLPH,
        NDST1, HID, 0LL, 0LL, 0LL);
    zstat_k<<<1, 128>>>();
    colstat_k<<<256, 128>>>(F_MLPH, NDST1);
    norm_k<<<256, 128>>>(F_MLPH, F_MLPH, gm, bem, NDST1, 1);
    sgemm_k<<<dim3(cdiv(OUTF, 128), cdiv(NDST1, 128), 1), 256>>>(
        nullptr, F_MLPH, Wm2, bm2, out, -1,
        NDST1, OUTF, HID, OUTF, OUTF);
}

// round 5
// speedup vs baseline: 1.5151x; 1.2183x over previous
#include <cuda_runtime.h>
#include <math.h>
#include <stdint.h>

// ---------------- problem constants ----------------
#define TREL   5
#define HEADS  4
#define HID    128
#define INFEAT 256
#define OUTF   153
#define NSRC0  120000
#define NDST0  40000
#define NDST1  10000
#define E0     800000
#define E1     300000
#define NEG    0.2f
#define EPSV   1e-5

// ---------------- device scratch (static, allowed) ----------------
__device__ __align__(16) float g_H0  [TREL * NSRC0 * HID];
__device__ __align__(16) float g_EL0 [NSRC0 * TREL * HEADS];
__device__ __align__(16) float g_ER0 [NDST0 * TREL * HEADS];
__device__ __align__(16) float g_SKIP0[NDST0 * HID];
__device__ __align__(16) float g_OUT0 [NDST0 * HID];
__device__ __align__(16) float g_H1  [TREL * NDST0 * HID];
__device__ __align__(16) float g_EL1 [NDST0 * TREL * HEADS];
__device__ __align__(16) float g_ER1 [NDST1 * TREL * HEADS];
__device__ __align__(16) float g_SKIP1[NDST1 * HID];
__device__ __align__(16) float g_OUT1 [NDST1 * HID];
__device__ __align__(16) float g_MLPH [NDST1 * HID];

__device__ int g_cnt0 [TREL * NDST0];
__device__ int g_off0 [TREL * (NDST0 + 1)];
__device__ int g_cur0 [TREL * NDST0];
__device__ int g_perm0[TREL * E0];
__device__ int g_cnt1 [TREL * NDST1];
__device__ int g_off1 [TREL * (NDST1 + 1)];
__device__ int g_cur1 [TREL * NDST1];
__device__ int g_perm1[TREL * E1];

__device__ double g_sum[HID];
__device__ double g_sq [HID];

enum {
    F_H0 = 0, F_EL0, F_ER0, F_SKIP0, F_OUT0,
    F_H1, F_EL1, F_ER1, F_SKIP1, F_OUT1, F_MLPH
};
enum {
    I_CNT0 = 0, I_OFF0, I_CUR0, I_PERM0,
    I_CNT1, I_OFF1, I_CUR1, I_PERM1
};

__device__ __forceinline__ float* FBUF(int id) {
    switch (id) {
        case F_H0:    return g_H0;
        case F_EL0:   return g_EL0;
        case F_ER0:   return g_ER0;
        case F_SKIP0: return g_SKIP0;
        case F_OUT0:  return g_OUT0;
        case F_H1:    return g_H1;
        case F_EL1:   return g_EL1;
        case F_ER1:   return g_ER1;
        case F_SKIP1: return g_SKIP1;
        case F_OUT1:  return g_OUT1;
        case F_MLPH:  return g_MLPH;
    }
    return nullptr;
}
__device__ __forceinline__ int* IBUF(int id) {
    switch (id) {
        case I_CNT0:  return g_cnt0;
        case I_OFF0:  return g_off0;
        case I_CUR0:  return g_cur0;
        case I_PERM0: return g_perm0;
        case I_CNT1:  return g_cnt1;
        case I_OFF1:  return g_off1;
        case I_CUR1:  return g_cur1;
        case I_PERM1: return g_perm1;
    }
    return nullptr;
}

__device__ __forceinline__ float lrelu(float z) { return z > 0.f ? z : NEG * z; }

// ---------------- bf16 split helpers ----------------
// hi/lo packed bf16x2: element with LOWER k index in LOWER 16 bits.
__device__ __forceinline__ void split2(float v0, float v1, uint32_t& hi, uint32_t& lo) {
    uint32_t h;
    asm("cvt.rn.bf16x2.f32 %0, %1, %2;" : "=r"(h) : "f"(v1), "f"(v0));
    float f0 = __uint_as_float(h << 16);
    float f1 = __uint_as_float(h & 0xffff0000u);
    uint32_t l;
    asm("cvt.rn.bf16x2.f32 %0, %1, %2;" : "=r"(l) : "f"(v1 - f1), "f"(v0 - f0));
    hi = h; lo = l;
}
__device__ __forceinline__ void mma_bf16(float* d, const uint32_t* a, const uint32_t* b) {
    asm volatile(
        "mma.sync.aligned.m16n8k16.row.col.f32.bf16.bf16.f32 "
        "{%0,%1,%2,%3}, {%4,%5,%6,%7}, {%8,%9}, {%0,%1,%2,%3};"
        : "+f"(d[0]), "+f"(d[1]), "+f"(d[2]), "+f"(d[3])
        : "r"(a[0]), "r"(a[1]), "r"(a[2]), "r"(a[3]), "r"(b[0]), "r"(b[1]));
}

// ---------------- tensor-core GEMM: C[M,128] = A[M,K] @ B[K,128] (+bias) ----------------
// bf16 2-way split, 3 products -> ~fp32 accuracy. N fixed 128, K mult of 32. Batch in z.
#define APAD 36
#define BPAD 132
__global__ void __launch_bounds__(256)
mma_gemm_k(const float* __restrict__ Aext, int Aid,
           const float* __restrict__ Bg, const float* __restrict__ bias,
           float* __restrict__ Cext, int Cid,
           int M, int K,
           long long Abatch, long long Bbatch, long long Cbatch)
{
    const float* A = (Aext ? Aext : FBUF(Aid)) + (size_t)blockIdx.z * Abatch;
    const float* B = Bg + (size_t)blockIdx.z * Bbatch;
    float*       C = (Cext ? Cext : FBUF(Cid)) + (size_t)blockIdx.z * Cbatch;

    __shared__ float As[128 * APAD];
    __shared__ float Bs[32 * BPAD];

    int tid  = threadIdx.x;
    int warp = tid >> 5, lane = tid & 31;
    int g = lane >> 2, t4 = lane & 3;
    int wr = (warp & 3) * 32;     // warp rows within 128
    int wc = (warp >> 2) * 64;    // warp cols within 128
    int row0 = blockIdx.y * 128;

    float acc[2][8][4];
    #pragma unroll
    for (int mi = 0; mi < 2; mi++)
        #pragma unroll
        for (int ni = 0; ni < 8; ni++)
            #pragma unroll
            for (int q = 0; q < 4; q++) acc[mi][ni][q] = 0.f;

    for (int kt = 0; kt < K; kt += 32) {
        // stage A: 128 x 32 fp32
        #pragma unroll
        for (int l = 0; l < 4; l++) {
            int s  = tid + l * 256;          // 1024 float4 slots
            int r  = s >> 3;
            int c4 = (s & 7) * 4;
            int rg = row0 + r;
            float4 v = make_float4(0.f, 0.f, 0.f, 0.f);
            if (rg < M) v = *(const float4*)&A[(size_t)rg * K + kt + c4];
            As[r * APAD + c4 + 0] = v.x;
            As[r * APAD + c4 + 1] = v.y;
            As[r * APAD + c4 + 2] = v.z;
            As[r * APAD + c4 + 3] = v.w;
        }
        // stage B: 32 x 128 fp32 (BPAD mult of 4 -> aligned float4 stores)
        #pragma unroll
        for (int l = 0; l < 4; l++) {
            int s  = tid + l * 256;
            int r  = s >> 5;
            int c4 = (s & 31) * 4;
            float4 v = *(const float4*)&B[(size_t)(kt + r) * 128 + c4];
            *(float4*)&Bs[r * BPAD + c4] = v;
        }
        __syncthreads();

        #pragma unroll
        for (int s16 = 0; s16 < 2; s16++) {
            int ks = s16 * 16;
            // A fragments (hi/lo) for 2 M-atoms, k16
            uint32_t ah[2][4], al[2][4];
            #pragma unroll
            for (int mi = 0; mi < 2; mi++) {
                int r0 = wr + mi * 16 + g;
                float2 v0 = *(const float2*)&As[(r0    ) * APAD + ks + 2 * t4    ];
                float2 v1 = *(const float2*)&As[(r0 + 8) * APAD + ks + 2 * t4    ];
                float2 v2 = *(const float2*)&As[(r0    ) * APAD + ks + 2 * t4 + 8];
                float2 v3 = *(const float2*)&As[(r0 + 8) * APAD + ks + 2 * t4 + 8];
                split2(v0.x, v0.y, ah[mi][0], al[mi][0]);
                split2(v1.x, v1.y, ah[mi][1], al[mi][1]);
                split2(v2.x, v2.y, ah[mi][2], al[mi][2]);
                split2(v3.x, v3.y, ah[mi][3], al[mi][3]);
            }
            #pragma unroll
            for (int ni = 0; ni < 8; ni++) {
                int c0 = wc + ni * 8 + g;
                float b00 = Bs[(ks + 2 * t4    ) * BPAD + c0];
                float b01 = Bs[(ks + 2 * t4 + 1) * BPAD + c0];
                float b10 = Bs[(ks + 2 * t4 + 8) * BPAD + c0];
                float b11 = Bs[(ks + 2 * t4 + 9) * BPAD + c0];
                uint32_t bh[2], bl[2];
                split2(b00, b01, bh[0], bl[0]);
                split2(b10, b11, bh[1], bl[1]);
                #pragma unroll
                for (int mi = 0; mi < 2; mi++) {
                    mma_bf16(acc[mi][ni], ah[mi], bh);   // hi*hi
                    mma_bf16(acc[mi][ni], al[mi], bh);   // lo*hi
                    mma_bf16(acc[mi][ni], ah[mi], bl);   // hi*lo
                }
            }
        }
        __syncthreads();
    }

    // epilogue (C fragment: c0,c1 = row g cols 2t,2t+1; c2,c3 = row g+8)
    #pragma unroll
    for (int mi = 0; mi < 2; mi++) {
        int r0 = row0 + wr + mi * 16 + g;
        #pragma unroll
        for (int ni = 0; ni < 8; ni++) {
            int c0 = wc + ni * 8 + t4 * 2;
            float bz0 = bias ? bias[c0] : 0.f;
            float bz1 = bias ? bias[c0 + 1] : 0.f;
            if (r0 < M) {
                float2 v = make_float2(acc[mi][ni][0] + bz0, acc[mi][ni][1] + bz1);
                *(float2*)&C[(size_t)r0 * 128 + c0] = v;
            }
            if (r0 + 8 < M) {
                float2 v = make_float2(acc[mi][ni][2] + bz0, acc[mi][ni][3] + bz1);
                *(float2*)&C[(size_t)(r0 + 8) * 128 + c0] = v;
            }
        }
    }
}

// ---------------- FFMA SGEMM (final layer, N=153) ----------------
__global__ void __launch_bounds__(256)
sgemm_k(const float* __restrict__ Aext, int Aid,
        const float* __restrict__ Bg, const float* __restrict__ bias,
        float* __restrict__ Cext, int Cid,
        int M, int N, int K, int ldb, int ldc)
{
    const float* A = (Aext ? Aext : FBUF(Aid));
    const float* B = Bg;
    float*       C = (Cext ? Cext : FBUF(Cid));

    __shared__ float As[16][128];
    __shared__ float Bs[16][128];

    int tid  = threadIdx.x;
    int row0 = blockIdx.y * 128;
    int col0 = blockIdx.x * 128;
    int ty = tid >> 4, tx = tid & 15;

    float acc[8][8];
    #pragma unroll
    for (int i = 0; i < 8; i++)
        #pragma unroll
        for (int j = 0; j < 8; j++) acc[i][j] = 0.f;

    for (int kt = 0; kt < K; kt += 16) {
        #pragma unroll
        for (int l = 0; l < 2; l++) {
            int s  = tid + l * 256;
            int r  = s >> 2;
            int c4 = (s & 3) * 4;
            int rg = row0 + r;
            float4 v = make_float4(0.f, 0.f, 0.f, 0.f);
            if (rg < M) v = *(const float4*)&A[(size_t)rg * K + kt + c4];
            As[c4 + 0][r] = v.x; As[c4 + 1][r] = v.y;
            As[c4 + 2][r] = v.z; As[c4 + 3][r] = v.w;
        }
        #pragma unroll
        for (int l = 0; l < 8; l++) {
            int s  = tid + l * 256;
            int kk = s >> 7, cc = s & 127;
            int cg = col0 + cc;
            Bs[kk][cc] = (cg < N) ? B[(size_t)(kt + kk) * ldb + cg] : 0.f;
        }
        __syncthreads();
        #pragma unroll
        for (int kk = 0; kk < 16; kk++) {
            float a[8], b[8];
            *(float4*)&a[0] = *(const float4*)&As[kk][ty * 8];
            *(float4*)&a[4] = *(const float4*)&As[kk][ty * 8 + 4];
            *(float4*)&b[0] = *(const float4*)&Bs[kk][tx * 8];
            *(float4*)&b[4] = *(const float4*)&Bs[kk][tx * 8 + 4];
            #pragma unroll
            for (int i = 0; i < 8; i++)
                #pragma unroll
                for (int j = 0; j < 8; j++) acc[i][j] += a[i] * b[j];
        }
        __syncthreads();
    }
    #pragma unroll
    for (int i = 0; i < 8; i++) {
        int r = row0 + ty * 8 + i;
        if (r >= M) continue;
        #pragma unroll
        for (int j = 0; j < 8; j++) {
            int c = col0 + tx * 8 + j;
            if (c < N) C[(size_t)r * ldc + c] = acc[i][j] + (bias ? bias[c] : 0.f);
        }
    }
}

// ---------------- el/er from H: one warp per (node, relation) ----------------
__global__ void eler_k(int Hid, const float* __restrict__ al, const float* __restrict__ ar,
                       int ELid, int ERid, int n_src, int n_dst)
{
    const float* Hb = FBUF(Hid);
    float* EL = FBUF(ELid);
    float* ER = FBUF(ERid);
    int w    = (blockIdx.x * blockDim.x + threadIdx.x) >> 5;
    int lane = threadIdx.x & 31;
    int total = n_src * TREL;
    if (w >= total) return;
    int j = w / n_src;
    int i = w - j * n_src;

    float4 hv = *(const float4*)&Hb[((size_t)j * n_src + i) * HID + lane * 4];
    float4 av = *(const float4*)&al[j * HID + lane * 4];
    float pl = hv.x * av.x + hv.y * av.y + hv.z * av.z + hv.w * av.w;
    float pr = 0.f;
    if (i < n_dst) {
        float4 rv = *(const float4*)&ar[j * HID + lane * 4];
        pr = hv.x * rv.x + hv.y * rv.y + hv.z * rv.z + hv.w * rv.w;
    }
    #pragma unroll
    for (int o = 4; o >= 1; o >>= 1) {
        pl += __shfl_down_sync(0xffffffffu, pl, o, 8);
        pr += __shfl_down_sync(0xffffffffu, pr, o, 8);
    }
    if ((lane & 7) == 0) {
        int h = lane >> 3;
        EL[(size_t)i * (TREL * HEADS) + j * HEADS + h] = pl;
        if (i < n_dst) ER[(size_t)i * (TREL * HEADS) + j * HEADS + h] = pr;
    }
}

// ---------------- CSR build ----------------
__global__ void zero_i_k(int id, int n) {
    int* p = IBUF(id);
    for (int i = blockIdx.x * blockDim.x + threadIdx.x; i < n; i += gridDim.x * blockDim.x)
        p[i] = 0;
}

__global__ void count_k(const int* __restrict__ dst, int E, int n_dst, int cntid) {
    int j = blockIdx.z;
    int* cnt = IBUF(cntid) + j * n_dst;
    const int* dj = dst + (size_t)j * E;
    for (int e = blockIdx.x * blockDim.x + threadIdx.x; e < E; e += gridDim.x * blockDim.x)
        atomicAdd(&cnt[dj[e]], 1);
}

__global__ void scan_k(int cntid, int offid, int n) {
    __shared__ int sh[1024];
    const int* cnt = IBUF(cntid) + blockIdx.x * n;
    int* off = IBUF(offid) + blockIdx.x * (n + 1);
    int carry = 0;
    for (int base = 0; base < n; base += 1024) {
        int i = base + threadIdx.x;
        int v = (i < n) ? cnt[i] : 0;
        sh[threadIdx.x] = v;
        __syncthreads();
        for (int o = 1; o < 1024; o <<= 1) {
            int t = (threadIdx.x >= o) ? sh[threadIdx.x - o] : 0;
            __syncthreads();
            sh[threadIdx.x] += t;
            __syncthreads();
        }
        if (i < n) off[i] = carry + sh[threadIdx.x] - v;
        int tot = sh[1023];
        __syncthreads();
        carry += tot;
    }
    if (threadIdx.x == 0) off[n] = carry;
}

__global__ void initcur_k(int offid, int curid, int n) {
    const int* off = IBUF(offid);
    int* cur = IBUF(curid);
    int tot = TREL * n;
    for (int idx = blockIdx.x * blockDim.x + threadIdx.x; idx < tot; idx += gridDim.x * blockDim.x) {
        int j = idx / n, d = idx - j * n;
        cur[idx] = off[j * (n + 1) + d];
    }
}

// perm stores the SRC NODE id directly
__global__ void fill_k(const int* __restrict__ dst, const int* __restrict__ src,
                       int E, int n_dst, int curid, int permid) {
    int j = blockIdx.z;
    int* cur  = IBUF(curid) + j * n_dst;
    int* perm = IBUF(permid) + (size_t)j * E;
    const int* dj = dst + (size_t)j * E;
    const int* sj = src + (size_t)j * E;
    for (int e = blockIdx.x * blockDim.x + threadIdx.x; e < E; e += gridDim.x * blockDim.x) {
        int pos = atomicAdd(&cur[dj[e]], 1);
        perm[pos] = sj[e];
    }
}

// ---------------- attention aggregation: single pass, one warp per dst, unroll 4 ----------------
__global__ void agg_k(int Hid, int ELid, int ERid,
                      int offid, int permid, int SKIPid, const float* __restrict__ b,
                      int OUTid, int n_src, int n_dst, int E)
{
    const float* Hb = FBUF(Hid);
    const float* EL = FBUF(ELid);
    const float* ER = FBUF(ERid);
    const float* SK = FBUF(SKIPid);
    float* OUTp = FBUF(OUTid);
    const int* off  = IBUF(offid);
    const int* perm = IBUF(permid);

    int w    = (blockIdx.x * blockDim.x + threadIdx.x) >> 5;
    int lane = threadIdx.x & 31;
    if (w >= n_dst) return;
    int d = w;
    int h = lane >> 3;

    float4 acc = *(const float4*)&SK[(size_t)d * HID + lane * 4];
    #pragma unroll
    for (int j = 0; j < TREL; j++) {
        float4 bv = *(const float4*)&b[j * HID + lane * 4];
        acc.x += bv.x; acc.y += bv.y; acc.z += bv.z; acc.w += bv.w;
    }

    for (int j = 0; j < TREL; j++) {
        int s0 = off[j * (n_dst + 1) + d];
        int s1 = off[j * (n_dst + 1) + d + 1];
        if (s1 == s0) continue;
        float erh = ER[(size_t)d * (TREL * HEADS) + j * HEADS + h];
        const int* pj = perm + (size_t)j * E;
        const float* Hj = Hb + (size_t)j * n_src * HID;

        float4 racc = make_float4(0.f, 0.f, 0.f, 0.f);
        float z = 0.f;
        int p = s0;
        for (; p + 3 < s1; p += 4) {
            int sA = pj[p], sB = pj[p + 1], sC = pj[p + 2], sD = pj[p + 3];
            float eA = EL[(size_t)sA * (TREL * HEADS) + j * HEADS + h];
            float eB = EL[(size_t)sB * (TREL * HEADS) + j * HEADS + h];
            float eC = EL[(size_t)sC * (TREL * HEADS) + j * HEADS + h];
            float eD = EL[(size_t)sD * (TREL * HEADS) + j * HEADS + h];
            float4 hA = *(const float4*)&Hj[(size_t)sA * HID + lane * 4];
            float4 hB = *(const float4*)&Hj[(size_t)sB * HID + lane * 4];
            float4 hC = *(const float4*)&Hj[(size_t)sC * HID + lane * 4];
            float4 hD = *(const float4*)&Hj[(size_t)sD * HID + lane * 4];
            float wA = __expf(fminf(lrelu(eA + erh), 80.f));
            float wB = __expf(fminf(lrelu(eB + erh), 80.f));
            float wC = __expf(fminf(lrelu(eC + erh), 80.f));
            float wD = __expf(fminf(lrelu(eD + erh), 80.f));
            z += (wA + wB) + (wC + wD);
            racc.x += wA * hA.x + wB * hB.x + wC * hC.x + wD * hD.x;
            racc.y += wA * hA.y + wB * hB.y + wC * hC.y + wD * hD.y;
            racc.z += wA * hA.z + wB * hB.z + wC * hC.z + wD * hD.z;
            racc.w += wA * hA.w + wB * hB.w + wC * hC.w + wD * hD.w;
        }
        for (; p < s1; p++) {
            int sA = pj[p];
            float eA = EL[(size_t)sA * (TREL * HEADS) + j * HEADS + h];
            float4 hA = *(const float4*)&Hj[(size_t)sA * HID + lane * 4];
            float wA = __expf(fminf(lrelu(eA + erh), 80.f));
            z += wA;
            racc.x += wA * hA.x; racc.y += wA * hA.y;
            racc.z += wA * hA.z; racc.w += wA * hA.w;
        }
        float inv = 1.f / (z + 1e-16f);
        acc.x += racc.x * inv; acc.y += racc.y * inv;
        acc.z += racc.z * inv; acc.w += racc.w * inv;
    }
    *(float4*)&OUTp[(size_t)d * HID + lane * 4] = acc;
}

// ---------------- column statistics + normalize + activation ----------------
__global__ void zstat_k() {
    int t = threadIdx.x;
    if (t < HID) { g_sum[t] = 0.0; g_sq[t] = 0.0; }
}

__global__ void colstat_k(int Xid, int n) {
    const float* X = FBUF(Xid);
    int c = threadIdx.x;
    float s = 0.f, q = 0.f;
    for (int r = blockIdx.x * 2; r < n; r += gridDim.x * 2) {
        float v = X[(size_t)r * HID + c];
        s += v; q += v * v;
        int r2 = r + 1;
        if (r2 < n) {
            float v2 = X[(size_t)r2 * HID + c];
            s += v2; q += v2 * v2;
        }
    }
    atomicAdd(&g_sum[c], (double)s);
    atomicAdd(&g_sq [c], (double)q);
}

// act: 0 = elu, 1 = relu
__global__ void norm_k(int Xid, int Yid, const float* __restrict__ g,
                       const float* __restrict__ be, int n, int act)
{
    const float* X = FBUF(Xid);
    float* Y = FBUF(Yid);
    int c = threadIdx.x;
    double mean = g_sum[c] / (double)n;
    double var  = g_sq[c] / (double)n - mean * mean;
    float fm = (float)mean;
    float sc = (float)(1.0 / sqrt(var + EPSV));
    float gg = g[c] * sc;
    float bb = be[c];
    for (int r = blockIdx.x; r < n; r += gridDim.x) {
        float v = (X[(size_t)r * HID + c] - fm) * gg + bb;
        float y;
        if (act == 0) y = v > 0.f ? v : expm1f(v);
        else          y = v > 0.f ? v : 0.f;
        Y[(size_t)r * HID + c] = y;
    }
}

static inline int cdiv(int a, int b) { return (a + b - 1) / b; }

// ---------------- launcher ----------------
extern "C" void kernel_launch(void* const* d_in, const int* in_sizes, int n_in,
                              void* d_out, int out_size)
{
    const float* x    = (const float*)d_in[0];
    const float* W0   = (const float*)d_in[1];
    const float* al0  = (const float*)d_in[2];
    const float* ar0  = (const float*)d_in[3];
    const float* b0   = (const float*)d_in[4];
    const float* Ws0  = (const float*)d_in[5];
    const float* bs0  = (const float*)d_in[6];
    const float* g0   = (const float*)d_in[7];
    const float* be0  = (const float*)d_in[8];
    const float* W1   = (const float*)d_in[9];
    const float* al1  = (const float*)d_in[10];
    const float* ar1  = (const float*)d_in[11];
    const float* b1   = (const float*)d_in[12];
    const float* Ws1  = (const float*)d_in[13];
    const float* bs1  = (const float*)d_in[14];
    const float* g1   = (const float*)d_in[15];
    const float* be1  = (const float*)d_in[16];
    const float* Wm1  = (const float*)d_in[17];
    const float* bm1  = (const float*)d_in[18];
    const float* gm   = (const float*)d_in[19];
    const float* bem  = (const float*)d_in[20];
    const float* Wm2  = (const float*)d_in[21];
    const float* bm2  = (const float*)d_in[22];
    const int*   src0 = (const int*)d_in[23];
    const int*   dst0 = (const int*)d_in[24];
    const int*   src1 = (const int*)d_in[25];
    const int*   dst1 = (const int*)d_in[26];
    float* out = (float*)d_out;

    // ===== Layer 0 (CSR first so the big GEMM lands in the profiled launch slot) =====
    zero_i_k<<<256, 256>>>(I_CNT0, TREL * NDST0);
    count_k<<<dim3(1024, 1, TREL), 256>>>(dst0, E0, NDST0, I_CNT0);
    scan_k<<<TREL, 1024>>>(I_CNT0, I_OFF0, NDST0);
    mma_gemm_k<<<dim3(1, cdiv(NSRC0, 128), TREL), 256>>>(       // launch #4: H0 = x @ W0[j]
        x, -1, W0, nullptr, nullptr, F_H0,
        NSRC0, INFEAT, 0LL, (long long)INFEAT * HID, (long long)NSRC0 * HID);
    mma_gemm_k<<<dim3(1, cdiv(NDST0, 128), 1), 256>>>(
        x, -1, Ws0, bs0, nullptr, F_SKIP0,
        NDST0, INFEAT, 0LL, 0LL, 0LL);
    eler_k<<<cdiv(NSRC0 * TREL * 32, 256), 256>>>(F_H0, al0, ar0, F_EL0, F_ER0, NSRC0, NDST0);
    initcur_k<<<256, 256>>>(I_OFF0, I_CUR0, NDST0);
    fill_k<<<dim3(1024, 1, TREL), 256>>>(dst0, src0, E0, NDST0, I_CUR0, I_PERM0);
    agg_k<<<cdiv(NDST0 * 32, 256), 256>>>(F_H0, F_EL0, F_ER0, I_OFF0, I_PERM0,
                                          F_SKIP0, b0, F_OUT0, NSRC0, NDST0, E0);
    zstat_k<<<1, 128>>>();
    colstat_k<<<512, 128>>>(F_OUT0, NDST0);
    norm_k<<<512, 128>>>(F_OUT0, F_OUT0, g0, be0, NDST0, 0);

    // ===== Layer 1 =====
    mma_gemm_k<<<dim3(1, cdiv(NDST0, 128), TREL), 256>>>(
        nullptr, F_OUT0, W1, nullptr, nullptr, F_H1,
        NDST0, HID, 0LL, (long long)HID * HID, (long long)NDST0 * HID);
    mma_gemm_k<<<dim3(1, cdiv(NDST1, 128), 1), 256>>>(
        nullptr, F_OUT0, Ws1, bs1, nullptr, F_SKIP1,
        NDST1, HID, 0LL, 0LL, 0LL);
    eler_k<<<cdiv(NDST0 * TREL * 32, 256), 256>>>(F_H1, al1, ar1, F_EL1, F_ER1, NDST0, NDST1);
    zero_i_k<<<256, 256>>>(I_CNT1, TREL * NDST1);
    count_k<<<dim3(512, 1, TREL), 256>>>(dst1, E1, NDST1, I_CNT1);
    scan_k<<<TREL, 1024>>>(I_CNT1, I_OFF1, NDST1);
    initcur_k<<<256, 256>>>(I_OFF1, I_CUR1, NDST1);
    fill_k<<<dim3(512, 1, TREL), 256>>>(dst1, src1, E1, NDST1, I_CUR1, I_PERM1);
    agg_k<<<cdiv(NDST1 * 32, 256), 256>>>(F_H1, F_EL1, F_ER1, I_OFF1, I_PERM1,
                                          F_SKIP1, b1, F_OUT1, NDST0, NDST1, E1);
    zstat_k<<<1, 128>>>();
    colstat_k<<<512, 128>>>(F_OUT1, NDST1);
    norm_k<<<512, 128>>>(F_OUT1, F_OUT1, g1, be1, NDST1, 0);

    // ===== MLP =====
    mma_gemm_k<<<dim3(1, cdiv(NDST1, 128), 1), 256>>>(
        nullptr, F_OUT1, Wm1, bm1, nullptr, F_MLPH,
        NDST1, HID, 0LL, 0LL, 0LL);
    zstat_k<<<1, 128>>>();
    colstat_k<<<512, 128>>>(F_MLPH, NDST1);
    norm_k<<<512, 128>>>(F_MLPH, F_MLPH, gm, bem, NDST1, 1);
    sgemm_k<<<dim3(cdiv(OUTF, 128), cdiv(NDST1, 128), 1), 256>>>(
        nullptr, F_MLPH, Wm2, bm2, out, -1,
        NDST1, OUTF, HID, OUTF, OUTF);
}

// round 7
// speedup vs baseline: 1.7118x; 1.1298x over previous
#include <cuda_runtime.h>
#include <math.h>
#include <stdint.h>

// ---------------- problem constants ----------------
#define TREL   5
#define HEADS  4
#define HID    128
#define INFEAT 256
#define OUTF   153
#define NSRC0  120000
#define NDST0  40000
#define NDST1  10000
#define E0     800000
#define E1     300000
#define NEG    0.2f
#define EPSV   1e-5

// ---------------- device scratch (static, allowed) ----------------
__device__ __align__(16) float g_H0  [TREL * NSRC0 * HID];
__device__ __align__(16) float g_EL0 [NSRC0 * TREL * HEADS];
__device__ __align__(16) float g_ER0 [NDST0 * TREL * HEADS];
__device__ __align__(16) float g_SKIP0[NDST0 * HID];
__device__ __align__(16) float g_OUT0 [NDST0 * HID];
__device__ __align__(16) float g_H1  [TREL * NDST0 * HID];
__device__ __align__(16) float g_EL1 [NDST0 * TREL * HEADS];
__device__ __align__(16) float g_ER1 [NDST1 * TREL * HEADS];
__device__ __align__(16) float g_SKIP1[NDST1 * HID];
__device__ __align__(16) float g_OUT1 [NDST1 * HID];
__device__ __align__(16) float g_MLPH [NDST1 * HID];

// packed bf16x2 split operands
__device__ __align__(16) uint32_t g_ASh[NSRC0 * (INFEAT / 2)];
__device__ __align__(16) uint32_t g_ASl[NSRC0 * (INFEAT / 2)];
__device__ __align__(16) uint32_t g_BSh[TREL * (INFEAT / 2) * HID];
__device__ __align__(16) uint32_t g_BSl[TREL * (INFEAT / 2) * HID];

__device__ int g_cnt0 [TREL * NDST0];
__device__ int g_off0 [TREL * (NDST0 + 1)];
__device__ int g_cur0 [TREL * NDST0];
__device__ int g_perm0[TREL * E0];
__device__ int g_cnt1 [TREL * NDST1];
__device__ int g_off1 [TREL * (NDST1 + 1)];
__device__ int g_cur1 [TREL * NDST1];
__device__ int g_perm1[TREL * E1];

__device__ double g_sum[HID];
__device__ double g_sq [HID];

enum {
    F_H0 = 0, F_EL0, F_ER0, F_SKIP0, F_OUT0,
    F_H1, F_EL1, F_ER1, F_SKIP1, F_OUT1, F_MLPH
};
enum {
    I_CNT0 = 0, I_OFF0, I_CUR0, I_PERM0,
    I_CNT1, I_OFF1, I_CUR1, I_PERM1
};

__device__ __forceinline__ float* FBUF(int id) {
    switch (id) {
        case F_H0:    return g_H0;
        case F_EL0:   return g_EL0;
        case F_ER0:   return g_ER0;
        case F_SKIP0: return g_SKIP0;
        case F_OUT0:  return g_OUT0;
        case F_H1:    return g_H1;
        case F_EL1:   return g_EL1;
        case F_ER1:   return g_ER1;
        case F_SKIP1: return g_SKIP1;
        case F_OUT1:  return g_OUT1;
        case F_MLPH:  return g_MLPH;
    }
    return nullptr;
}
__device__ __forceinline__ int* IBUF(int id) {
    switch (id) {
        case I_CNT0:  return g_cnt0;
        case I_OFF0:  return g_off0;
        case I_CUR0:  return g_cur0;
        case I_PERM0: return g_perm0;
        case I_CNT1:  return g_cnt1;
        case I_OFF1:  return g_off1;
        case I_CUR1:  return g_cur1;
        case I_PERM1: return g_perm1;
    }
    return nullptr;
}

__device__ __forceinline__ float lrelu(float z) { return z > 0.f ? z : NEG * z; }

// ---------------- bf16 split helpers ----------------
// packed bf16x2: element with LOWER k index in LOWER 16 bits.
__device__ __forceinline__ void split2(float v0, float v1, uint32_t& hi, uint32_t& lo) {
    uint32_t h;
    asm("cvt.rn.bf16x2.f32 %0, %1, %2;" : "=r"(h) : "f"(v1), "f"(v0));
    float f0 = __uint_as_float(h << 16);
    float f1 = __uint_as_float(h & 0xffff0000u);
    uint32_t l;
    asm("cvt.rn.bf16x2.f32 %0, %1, %2;" : "=r"(l) : "f"(v1 - f1), "f"(v0 - f0));
    hi = h; lo = l;
}
__device__ __forceinline__ void mma_bf16(float* d, const uint32_t* a, const uint32_t* b) {
    asm volatile(
        "mma.sync.aligned.m16n8k16.row.col.f32.bf16.bf16.f32 "
        "{%0,%1,%2,%3}, {%4,%5,%6,%7}, {%8,%9}, {%0,%1,%2,%3};"
        : "+f"(d[0]), "+f"(d[1]), "+f"(d[2]), "+f"(d[3])
        : "r"(a[0]), "r"(a[1]), "r"(a[2]), "r"(a[3]), "r"(b[0]), "r"(b[1]));
}

// ---------------- operand split kernels ----------------
// A[M][K] fp32 (contiguous) -> ASh/ASl uint32 [M][K/2]
__global__ void splitA_k(const float* __restrict__ Aext, int Aid, int tot /* = M*K/2 */) {
    const float* A = Aext ? Aext : FBUF(Aid);
    for (int idx = blockIdx.x * blockDim.x + threadIdx.x; idx < tot; idx += gridDim.x * blockDim.x) {
        float2 v = *(const float2*)&A[2 * idx];
        uint32_t h, l;
        split2(v.x, v.y, h, l);
        g_ASh[idx] = h;
        g_ASl[idx] = l;
    }
}

// W[z][K][128] fp32 -> BSh/BSl uint32 [z][K/2][128]  (pack k-pairs per column)
__global__ void splitB_k(const float* __restrict__ W, int K) {
    int z = blockIdx.z;
    int K2 = K >> 1;
    const float* Wz = W + (size_t)z * K * HID;
    uint32_t* Bh = g_BSh + (size_t)z * K2 * HID;
    uint32_t* Bl = g_BSl + (size_t)z * K2 * HID;
    int tot = K2 * HID;
    for (int idx = blockIdx.x * blockDim.x + threadIdx.x; idx < tot; idx += gridDim.x * blockDim.x) {
        int k2 = idx >> 7, n = idx & 127;
        float v0 = Wz[(2 * k2    ) * HID + n];
        float v1 = Wz[(2 * k2 + 1) * HID + n];
        uint32_t h, l;
        split2(v0, v1, h, l);
        Bh[idx] = h;
        Bl[idx] = l;
    }
}

// ---------------- tensor-core GEMM on pre-split operands ----------------
// C[M,128] = A[M,K] @ B[K,128] (+bias). A = g_AS (batch-invariant), B = g_BS (batch z).
// K2 = K/2 in uint32 units, multiple of 16.
#define APAD2 20
#define BPAD2 132
__global__ void __launch_bounds__(256, 2)
mma_gemm2_k(int M, int K2, const float* __restrict__ bias, int Cid,
            long long Bbatch, long long Cbatch)
{
    const uint32_t* Ah = g_ASh;
    const uint32_t* Al = g_ASl;
    const uint32_t* Bh = g_BSh + (size_t)blockIdx.z * Bbatch;
    const uint32_t* Bl = g_BSl + (size_t)blockIdx.z * Bbatch;
    float* C = FBUF(Cid) + (size_t)blockIdx.z * Cbatch;

    __shared__ uint32_t AsH[128 * APAD2];
    __shared__ uint32_t AsL[128 * APAD2];
    __shared__ uint32_t BsH[16 * BPAD2];
    __shared__ uint32_t BsL[16 * BPAD2];

    int tid  = threadIdx.x;
    int warp = tid >> 5, lane = tid & 31;
    int g = lane >> 2, t4 = lane & 3;
    int wr = (warp & 3) * 32;     // warp rows within 128
    int wc = (warp >> 2) * 64;    // warp cols within 128
    int row0 = blockIdx.y * 128;

    float acc[2][8][4];
    #pragma unroll
    for (int mi = 0; mi < 2; mi++)
        #pragma unroll
        for (int ni = 0; ni < 8; ni++)
            #pragma unroll
            for (int q = 0; q < 4; q++) acc[mi][ni][q] = 0.f;

    for (int kt2 = 0; kt2 < K2; kt2 += 16) {
        // stage A: 128 rows x 16 u32, hi + lo
        #pragma unroll
        for (int l = 0; l < 2; l++) {
            int s  = tid + l * 256;         // 512 uint4 slots
            int r  = s >> 2;
            int c4 = (s & 3) * 4;
            int rg = row0 + r;
            uint4 vh = make_uint4(0u, 0u, 0u, 0u);
            uint4 vl = make_uint4(0u, 0u, 0u, 0u);
            if (rg < M) {
                size_t o = (size_t)rg * K2 + kt2 + c4;
                vh = *(const uint4*)&Ah[o];
                vl = *(const uint4*)&Al[o];
            }
            *(uint4*)&AsH[r * APAD2 + c4] = vh;
            *(uint4*)&AsL[r * APAD2 + c4] = vl;
        }
        // stage B: 16 rows x 128 u32, hi + lo
        #pragma unroll
        for (int l = 0; l < 2; l++) {
            int s  = tid + l * 256;
            int r  = s >> 5;
            int c4 = (s & 31) * 4;
            size_t o = (size_t)(kt2 + r) * HID + c4;
            *(uint4*)&BsH[r * BPAD2 + c4] = *(const uint4*)&Bh[o];
            *(uint4*)&BsL[r * BPAD2 + c4] = *(const uint4*)&Bl[o];
        }
        __syncthreads();

        #pragma unroll
        for (int s16 = 0; s16 < 2; s16++) {
            int ks2 = s16 * 8;
            uint32_t ah[2][4], al[2][4];
            #pragma unroll
            for (int mi = 0; mi < 2; mi++) {
                int r0 = wr + mi * 16 + g;
                ah[mi][0] = AsH[(r0    ) * APAD2 + ks2 + t4    ];
                ah[mi][1] = AsH[(r0 + 8) * APAD2 + ks2 + t4    ];
                ah[mi][2] = AsH[(r0    ) * APAD2 + ks2 + t4 + 4];
                ah[mi][3] = AsH[(r0 + 8) * APAD2 + ks2 + t4 + 4];
                al[mi][0] = AsL[(r0    ) * APAD2 + ks2 + t4    ];
                al[mi][1] = AsL[(r0 + 8) * APAD2 + ks2 + t4    ];
                al[mi][2] = AsL[(r0    ) * APAD2 + ks2 + t4 + 4];
                al[mi][3] = AsL[(r0 + 8) * APAD2 + ks2 + t4 + 4];
            }
            #pragma unroll
            for (int ni = 0; ni < 8; ni++) {
                int c0 = wc + ni * 8 + g;
                uint32_t bh[2], bl[2];
                bh[0] = BsH[(ks2 + t4    ) * BPAD2 + c0];
                bh[1] = BsH[(ks2 + t4 + 4) * BPAD2 + c0];
                bl[0] = BsL[(ks2 + t4    ) * BPAD2 + c0];
                bl[1] = BsL[(ks2 + t4 + 4) * BPAD2 + c0];
                #pragma unroll
                for (int mi = 0; mi < 2; mi++) {
                    mma_bf16(acc[mi][ni], ah[mi], bh);   // hi*hi
                    mma_bf16(acc[mi][ni], al[mi], bh);   // lo*hi
                    mma_bf16(acc[mi][ni], ah[mi], bl);   // hi*lo
                }
            }
        }
        __syncthreads();
    }

    // epilogue
    #pragma unroll
    for (int mi = 0; mi < 2; mi++) {
        int r0 = row0 + wr + mi * 16 + g;
        #pragma unroll
        for (int ni = 0; ni < 8; ni++) {
            int c0 = wc + ni * 8 + t4 * 2;
            float bz0 = bias ? bias[c0] : 0.f;
            float bz1 = bias ? bias[c0 + 1] : 0.f;
            if (r0 < M) {
                float2 v = make_float2(acc[mi][ni][0] + bz0, acc[mi][ni][1] + bz1);
                *(float2*)&C[(size_t)r0 * HID + c0] = v;
            }
            if (r0 + 8 < M) {
                float2 v = make_float2(acc[mi][ni][2] + bz0, acc[mi][ni][3] + bz1);
                *(float2*)&C[(size_t)(r0 + 8) * HID + c0] = v;
            }
        }
    }
}

// ---------------- FFMA SGEMM (final layer, N=153) ----------------
__global__ void __launch_bounds__(256)
sgemm_k(const float* __restrict__ Aext, int Aid,
        const float* __restrict__ Bg, const float* __restrict__ bias,
        float* __restrict__ Cext, int Cid,
        int M, int N, int K, int ldb, int ldc)
{
    const float* A = (Aext ? Aext : FBUF(Aid));
    const float* B = Bg;
    float*       C = (Cext ? Cext : FBUF(Cid));

    __shared__ float As[16][128];
    __shared__ float Bs[16][128];

    int tid  = threadIdx.x;
    int row0 = blockIdx.y * 128;
    int col0 = blockIdx.x * 128;
    int ty = tid >> 4, tx = tid & 15;

    float acc[8][8];
    #pragma unroll
    for (int i = 0; i < 8; i++)
        #pragma unroll
        for (int j = 0; j < 8; j++) acc[i][j] = 0.f;

    for (int kt = 0; kt < K; kt += 16) {
        #pragma unroll
        for (int l = 0; l < 2; l++) {
            int s  = tid + l * 256;
            int r  = s >> 2;
            int c4 = (s & 3) * 4;
            int rg = row0 + r;
            float4 v = make_float4(0.f, 0.f, 0.f, 0.f);
            if (rg < M) v = *(const float4*)&A[(size_t)rg * K + kt + c4];
            As[c4 + 0][r] = v.x; As[c4 + 1][r] = v.y;
            As[c4 + 2][r] = v.z; As[c4 + 3][r] = v.w;
        }
        #pragma unroll
        for (int l = 0; l < 8; l++) {
            int s  = tid + l * 256;
            int kk = s >> 7, cc = s & 127;
            int cg = col0 + cc;
            Bs[kk][cc] = (cg < N) ? B[(size_t)(kt + kk) * ldb + cg] : 0.f;
        }
        __syncthreads();
        #pragma unroll
        for (int kk = 0; kk < 16; kk++) {
            float a[8], b[8];
            *(float4*)&a[0] = *(const float4*)&As[kk][ty * 8];
            *(float4*)&a[4] = *(const float4*)&As[kk][ty * 8 + 4];
            *(float4*)&b[0] = *(const float4*)&Bs[kk][tx * 8];
            *(float4*)&b[4] = *(const float4*)&Bs[kk][tx * 8 + 4];
            #pragma unroll
            for (int i = 0; i < 8; i++)
                #pragma unroll
                for (int j = 0; j < 8; j++) acc[i][j] += a[i] * b[j];
        }
        __syncthreads();
    }
    #pragma unroll
    for (int i = 0; i < 8; i++) {
        int r = row0 + ty * 8 + i;
        if (r >= M) continue;
        #pragma unroll
        for (int j = 0; j < 8; j++) {
            int c = col0 + tx * 8 + j;
            if (c < N) C[(size_t)r * ldc + c] = acc[i][j] + (bias ? bias[c] : 0.f);
        }
    }
}

// ---------------- el/er from H: one warp per (node, relation) ----------------
__global__ void eler_k(int Hid, const float* __restrict__ al, const float* __restrict__ ar,
                       int ELid, int ERid, int n_src, int n_dst)
{
    const float* Hb = FBUF(Hid);
    float* EL = FBUF(ELid);
    float* ER = FBUF(ERid);
    int w    = (blockIdx.x * blockDim.x + threadIdx.x) >> 5;
    int lane = threadIdx.x & 31;
    int total = n_src * TREL;
    if (w >= total) return;
    int j = w / n_src;
    int i = w - j * n_src;

    float4 hv = *(const float4*)&Hb[((size_t)j * n_src + i) * HID + lane * 4];
    float4 av = *(const float4*)&al[j * HID + lane * 4];
    float pl = hv.x * av.x + hv.y * av.y + hv.z * av.z + hv.w * av.w;
    float pr = 0.f;
    if (i < n_dst) {
        float4 rv = *(const float4*)&ar[j * HID + lane * 4];
        pr = hv.x * rv.x + hv.y * rv.y + hv.z * rv.z + hv.w * rv.w;
    }
    #pragma unroll
    for (int o = 4; o >= 1; o >>= 1) {
        pl += __shfl_down_sync(0xffffffffu, pl, o, 8);
        pr += __shfl_down_sync(0xffffffffu, pr, o, 8);
    }
    if ((lane & 7) == 0) {
        int h = lane >> 3;
        EL[(size_t)i * (TREL * HEADS) + j * HEADS + h] = pl;
        if (i < n_dst) ER[(size_t)i * (TREL * HEADS) + j * HEADS + h] = pr;
    }
}

// ---------------- CSR build ----------------
__global__ void zero_i_k(int id, int n) {
    int* p = IBUF(id);
    for (int i = blockIdx.x * blockDim.x + threadIdx.x; i < n; i += gridDim.x * blockDim.x)
        p[i] = 0;
}

__global__ void count_k(const int* __restrict__ dst, int E, int n_dst, int cntid) {
    int j = blockIdx.z;
    int* cnt = IBUF(cntid) + j * n_dst;
    const int* dj = dst + (size_t)j * E;
    for (int e = blockIdx.x * blockDim.x + threadIdx.x; e < E; e += gridDim.x * blockDim.x)
        atomicAdd(&cnt[dj[e]], 1);
}

__global__ void scan_k(int cntid, int offid, int n) {
    __shared__ int sh[1024];
    const int* cnt = IBUF(cntid) + blockIdx.x * n;
    int* off = IBUF(offid) + blockIdx.x * (n + 1);
    int carry = 0;
    for (int base = 0; base < n; base += 1024) {
        int i = base + threadIdx.x;
        int v = (i < n) ? cnt[i] : 0;
        sh[threadIdx.x] = v;
        __syncthreads();
        for (int o = 1; o < 1024; o <<= 1) {
            int t = (threadIdx.x >= o) ? sh[threadIdx.x - o] : 0;
            __syncthreads();
            sh[threadIdx.x] += t;
            __syncthreads();
        }
        if (i < n) off[i] = carry + sh[threadIdx.x] - v;
        int tot = sh[1023];
        __syncthreads();
        carry += tot;
    }
    if (threadIdx.x == 0) off[n] = carry;
}

__global__ void initcur_k(int offid, int curid, int n) {
    const int* off = IBUF(offid);
    int* cur = IBUF(curid);
    int tot = TREL * n;
    for (int idx = blockIdx.x * blockDim.x + threadIdx.x; idx < tot; idx += gridDim.x * blockDim.x) {
        int j = idx / n, d = idx - j * n;
        cur[idx] = off[j * (n + 1) + d];
    }
}

// perm stores the SRC NODE id directly
__global__ void fill_k(const int* __restrict__ dst, const int* __restrict__ src,
                       int E, int n_dst, int curid, int permid) {
    int j = blockIdx.z;
    int* cur  = IBUF(curid) + j * n_dst;
    int* perm = IBUF(permid) + (size_t)j * E;
    const int* dj = dst + (size_t)j * E;
    const int* sj = src + (size_t)j * E;
    for (int e = blockIdx.x * blockDim.x + threadIdx.x; e < E; e += gridDim.x * blockDim.x) {
        int pos = atomicAdd(&cur[dj[e]], 1);
        perm[pos] = sj[e];
    }
}

// ---------------- attention aggregation: single pass, one warp per dst, unroll 4 ----------------
__global__ void agg_k(int Hid, int ELid, int ERid,
                      int offid, int permid, int SKIPid, const float* __restrict__ b,
                      int OUTid, int n_src, int n_dst, int E)
{
    const float* Hb = FBUF(Hid);
    const float* EL = FBUF(ELid);
    const float* ER = FBUF(ERid);
    const float* SK = FBUF(SKIPid);
    float* OUTp = FBUF(OUTid);
    const int* off  = IBUF(offid);
    const int* perm = IBUF(permid);

    int w    = (blockIdx.x * blockDim.x + threadIdx.x) >> 5;
    int lane = threadIdx.x & 31;
    if (w >= n_dst) return;
    int d = w;
    int h = lane >> 3;

    float4 acc = *(const float4*)&SK[(size_t)d * HID + lane * 4];
    #pragma unroll
    for (int j = 0; j < TREL; j++) {
        float4 bv = *(const float4*)&b[j * HID + lane * 4];
        acc.x += bv.x; acc.y += bv.y; acc.z += bv.z; acc.w += bv.w;
    }

    for (int j = 0; j < TREL; j++) {
        int s0 = off[j * (n_dst + 1) + d];
        int s1 = off[j * (n_dst + 1) + d + 1];
        if (s1 == s0) continue;
        float erh = ER[(size_t)d * (TREL * HEADS) + j * HEADS + h];
        const int* pj = perm + (size_t)j * E;
        const float* Hj = Hb + (size_t)j * n_src * HID;

        float4 racc = make_float4(0.f, 0.f, 0.f, 0.f);
        float z = 0.f;
        int p = s0;
        for (; p + 3 < s1; p += 4) {
            int sA = pj[p], sB = pj[p + 1], sC = pj[p + 2], sD = pj[p + 3];
            float eA = EL[(size_t)sA * (TREL * HEADS) + j * HEADS + h];
            float eB = EL[(size_t)sB * (TREL * HEADS) + j * HEADS + h];
            float eC = EL[(size_t)sC * (TREL * HEADS) + j * HEADS + h];
            float eD = EL[(size_t)sD * (TREL * HEADS) + j * HEADS + h];
            float4 hA = *(const float4*)&Hj[(size_t)sA * HID + lane * 4];
            float4 hB = *(const float4*)&Hj[(size_t)sB * HID + lane * 4];
            float4 hC = *(const float4*)&Hj[(size_t)sC * HID + lane * 4];
            float4 hD = *(const float4*)&Hj[(size_t)sD * HID + lane * 4];
            float wA = __expf(fminf(lrelu(eA + erh), 80.f));
            float wB = __expf(fminf(lrelu(eB + erh), 80.f));
            float wC = __expf(fminf(lrelu(eC + erh), 80.f));
            float wD = __expf(fminf(lrelu(eD + erh), 80.f));
            z += (wA + wB) + (wC + wD);
            racc.x += wA * hA.x + wB * hB.x + wC * hC.x + wD * hD.x;
            racc.y += wA * hA.y + wB * hB.y + wC * hC.y + wD * hD.y;
            racc.z += wA * hA.z + wB * hB.z + wC * hC.z + wD * hD.z;
            racc.w += wA * hA.w + wB * hB.w + wC * hC.w + wD * hD.w;
        }
        for (; p < s1; p++) {
            int sA = pj[p];
            float eA = EL[(size_t)sA * (TREL * HEADS) + j * HEADS + h];
            float4 hA = *(const float4*)&Hj[(size_t)sA * HID + lane * 4];
            float wA = __expf(fminf(lrelu(eA + erh), 80.f));
            z += wA;
            racc.x += wA * hA.x; racc.y += wA * hA.y;
            racc.z += wA * hA.z; racc.w += wA * hA.w;
        }
        float inv = 1.f / (z + 1e-16f);
        acc.x += racc.x * inv; acc.y += racc.y * inv;
        acc.z += racc.z * inv; acc.w += racc.w * inv;
    }
    *(float4*)&OUTp[(size_t)d * HID + lane * 4] = acc;
}

// ---------------- column statistics + normalize + activation ----------------
__global__ void zstat_k() {
    int t = threadIdx.x;
    if (t < HID) { g_sum[t] = 0.0; g_sq[t] = 0.0; }
}

__global__ void colstat_k(int Xid, int n) {
    const float* X = FBUF(Xid);
    int c = threadIdx.x;
    float s = 0.f, q = 0.f;
    for (int r = blockIdx.x * 2; r < n; r += gridDim.x * 2) {
        float v = X[(size_t)r * HID + c];
        s += v; q += v * v;
        int r2 = r + 1;
        if (r2 < n) {
            float v2 = X[(size_t)r2 * HID + c];
            s += v2; q += v2 * v2;
        }
    }
    atomicAdd(&g_sum[c], (double)s);
    atomicAdd(&g_sq [c], (double)q);
}

// act: 0 = elu, 1 = relu
__global__ void norm_k(int Xid, int Yid, const float* __restrict__ g,
                       const float* __restrict__ be, int n, int act)
{
    const float* X = FBUF(Xid);
    float* Y = FBUF(Yid);
    int c = threadIdx.x;
    double mean = g_sum[c] / (double)n;
    double var  = g_sq[c] / (double)n - mean * mean;
    float fm = (float)mean;
    float sc = (float)(1.0 / sqrt(var + EPSV));
    float gg = g[c] * sc;
    float bb = be[c];
    for (int r = blockIdx.x; r < n; r += gridDim.x) {
        float v = (X[(size_t)r * HID + c] - fm) * gg + bb;
        float y;
        if (act == 0) y = v > 0.f ? v : expm1f(v);
        else          y = v > 0.f ? v : 0.f;
        Y[(size_t)r * HID + c] = y;
    }
}

static inline int cdiv(int a, int b) { return (a + b - 1) / b; }

// ---------------- launcher ----------------
extern "C" void kernel_launch(void* const* d_in, const int* in_sizes, int n_in,
                              void* d_out, int out_size)
{
    const float* x    = (const float*)d_in[0];
    const float* W0   = (const float*)d_in[1];
    const float* al0  = (const float*)d_in[2];
    const float* ar0  = (const float*)d_in[3];
    const float* b0   = (const float*)d_in[4];
    const float* Ws0  = (const float*)d_in[5];
    const float* bs0  = (const float*)d_in[6];
    const float* g0   = (const float*)d_in[7];
    const float* be0  = (const float*)d_in[8];
    const float* W1   = (const float*)d_in[9];
    const float* al1  = (const float*)d_in[10];
    const float* ar1  = (const float*)d_in[11];
    const float* b1   = (const float*)d_in[12];
    const float* Ws1  = (const float*)d_in[13];
    const float* bs1  = (const float*)d_in[14];
    const float* g1   = (const float*)d_in[15];
    const float* be1  = (const float*)d_in[16];
    const float* Wm1  = (const float*)d_in[17];
    const float* bm1  = (const float*)d_in[18];
    const float* gm   = (const float*)d_in[19];
    const float* bem  = (const float*)d_in[20];
    const float* Wm2  = (const float*)d_in[21];
    const float* bm2  = (const float*)d_in[22];
    const int*   src0 = (const int*)d_in[23];
    const int*   dst0 = (const int*)d_in[24];
    const int*   src1 = (const int*)d_in[25];
    const int*   dst1 = (const int*)d_in[26];
    float* out = (float*)d_out;

    // ===== Layer 0 =====
    zero_i_k<<<256, 256>>>(I_CNT0, TREL * NDST0);
    count_k<<<dim3(1024, 1, TREL), 256>>>(dst0, E0, NDST0, I_CNT0);
    scan_k<<<TREL, 1024>>>(I_CNT0, I_OFF0, NDST0);
    splitB_k<<<dim3(64, 1, TREL), 256>>>(W0, INFEAT);
    splitA_k<<<2048, 256>>>(x, -1, NSRC0 * (INFEAT / 2));
    mma_gemm2_k<<<dim3(1, cdiv(NSRC0, 128), TREL), 256>>>(       // H0 = x @ W0[j]
        NSRC0, INFEAT / 2, nullptr, F_H0,
        (long long)(INFEAT / 2) * HID, (long long)NSRC0 * HID);
    splitB_k<<<dim3(64, 1, 1), 256>>>(Ws0, INFEAT);
    mma_gemm2_k<<<dim3(1, cdiv(NDST0, 128), 1), 256>>>(          // SKIP0 = x[:40000] @ Ws0 + bs0
        NDST0, INFEAT / 2, bs0, F_SKIP0, 0LL, 0LL);
    eler_k<<<cdiv(NSRC0 * TREL * 32, 256), 256>>>(F_H0, al0, ar0, F_EL0, F_ER0, NSRC0, NDST0);
    initcur_k<<<256, 256>>>(I_OFF0, I_CUR0, NDST0);
    fill_k<<<dim3(1024, 1, TREL), 256>>>(dst0, src0, E0, NDST0, I_CUR0, I_PERM0);
    agg_k<<<cdiv(NDST0 * 32, 256), 256>>>(F_H0, F_EL0, F_ER0, I_OFF0, I_PERM0,
                                          F_SKIP0, b0, F_OUT0, NSRC0, NDST0, E0);
    zstat_k<<<1, 128>>>();
    colstat_k<<<512, 128>>>(F_OUT0, NDST0);
    norm_k<<<512, 128>>>(F_OUT0, F_OUT0, g0, be0, NDST0, 0);

    // ===== Layer 1 =====
    splitA_k<<<1024, 256>>>(nullptr, F_OUT0, NDST0 * (HID / 2));
    splitB_k<<<dim3(32, 1, TREL), 256>>>(W1, HID);
    mma_gemm2_k<<<dim3(1, cdiv(NDST0, 128), TREL), 256>>>(       // H1 = OUT0 @ W1[j]
        NDST0, HID / 2, nullptr, F_H1,
        (long long)(HID / 2) * HID, (long long)NDST0 * HID);
    splitB_k<<<dim3(32, 1, 1), 256>>>(Ws1, HID);
    mma_gemm2_k<<<dim3(1, cdiv(NDST1, 128), 1), 256>>>(          // SKIP1
        NDST1, HID / 2, bs1, F_SKIP1, 0LL, 0LL);
    eler_k<<<cdiv(NDST0 * TREL * 32, 256), 256>>>(F_H1, al1, ar1, F_EL1, F_ER1, NDST0, NDST1);
    zero_i_k<<<256, 256>>>(I_CNT1, TREL * NDST1);
    count_k<<<dim3(512, 1, TREL), 256>>>(dst1, E1, NDST1, I_CNT1);
    scan_k<<<TREL, 1024>>>(I_CNT1, I_OFF1, NDST1);
    initcur_k<<<256, 256>>>(I_OFF1, I_CUR1, NDST1);
    fill_k<<<dim3(512, 1, TREL), 256>>>(dst1, src1, E1, NDST1, I_CUR1, I_PERM1);
    agg_k<<<cdiv(NDST1 * 32, 256), 256>>>(F_H1, F_EL1, F_ER1, I_OFF1, I_PERM1,
                                          F_SKIP1, b1, F_OUT1, NDST0, NDST1, E1);
    zstat_k<<<1, 128>>>();
    colstat_k<<<512, 128>>>(F_OUT1, NDST1);
    norm_k<<<512, 128>>>(F_OUT1, F_OUT1, g1, be1, NDST1, 0);

    // ===== MLP =====
    splitA_k<<<512, 256>>>(nullptr, F_OUT1, NDST1 * (HID / 2));
    splitB_k<<<dim3(32, 1, 1), 256>>>(Wm1, HID);
    mma_gemm2_k<<<dim3(1, cdiv(NDST1, 128), 1), 256>>>(
        NDST1, HID / 2, bm1, F_MLPH, 0LL, 0LL);
    zstat_k<<<1, 128>>>();
    colstat_k<<<512, 128>>>(F_MLPH, NDST1);
    norm_k<<<512, 128>>>(F_MLPH, F_MLPH, gm, bem, NDST1, 1);
    sgemm_k<<<dim3(cdiv(OUTF, 128), cdiv(NDST1, 128), 1), 256>>>(
        nullptr, F_MLPH, Wm2, bm2, out, -1,
        NDST1, OUTF, HID, OUTF, OUTF);
}

// round 9
// speedup vs baseline: 1.7598x; 1.0281x over previous
#include <cuda_runtime.h>
#include <math.h>
#include <stdint.h>

// ---------------- problem constants ----------------
#define TREL   5
#define HEADS  4
#define HID    128
#define INFEAT 256
#define OUTF   153
#define NSRC0  120000
#define NDST0  40000
#define NDST1  10000
#define E0     800000
#define E1     300000
#define NEG    0.2f
#define EPSV   1e-5

// ---------------- device scratch (static, allowed) ----------------
__device__ __align__(16) float g_H0  [TREL * NSRC0 * HID];
__device__ __align__(16) float g_EL0 [NSRC0 * TREL * HEADS];
__device__ __align__(16) float g_ER0 [NDST0 * TREL * HEADS];
__device__ __align__(16) float g_SKIP0[NDST0 * HID];
__device__ __align__(16) float g_OUT0 [NDST0 * HID];
__device__ __align__(16) float g_H1  [TREL * NDST0 * HID];
__device__ __align__(16) float g_EL1 [NDST0 * TREL * HEADS];
__device__ __align__(16) float g_ER1 [NDST1 * TREL * HEADS];
__device__ __align__(16) float g_SKIP1[NDST1 * HID];
__device__ __align__(16) float g_OUT1 [NDST1 * HID];
__device__ __align__(16) float g_MLPH [NDST1 * HID];

// packed bf16x2 split operands
__device__ __align__(16) uint32_t g_ASh[NSRC0 * (INFEAT / 2)];
__device__ __align__(16) uint32_t g_ASl[NSRC0 * (INFEAT / 2)];
__device__ __align__(16) uint32_t g_BSh[TREL * (INFEAT / 2) * HID];
__device__ __align__(16) uint32_t g_BSl[TREL * (INFEAT / 2) * HID];

__device__ int g_cnt0 [TREL * NDST0];
__device__ int g_off0 [TREL * (NDST0 + 1)];
__device__ int g_cur0 [TREL * NDST0];
__device__ int g_perm0[TREL * E0];
__device__ int g_cnt1 [TREL * NDST1];
__device__ int g_off1 [TREL * (NDST1 + 1)];
__device__ int g_cur1 [TREL * NDST1];
__device__ int g_perm1[TREL * E1];

__device__ double g_sum[HID];
__device__ double g_sq [HID];

enum {
    F_H0 = 0, F_EL0, F_ER0, F_SKIP0, F_OUT0,
    F_H1, F_EL1, F_ER1, F_SKIP1, F_OUT1, F_MLPH
};
enum {
    I_CNT0 = 0, I_OFF0, I_CUR0, I_PERM0,
    I_CNT1, I_OFF1, I_CUR1, I_PERM1
};

__device__ __forceinline__ float* FBUF(int id) {
    switch (id) {
        case F_H0:    return g_H0;
        case F_EL0:   return g_EL0;
        case F_ER0:   return g_ER0;
        case F_SKIP0: return g_SKIP0;
        case F_OUT0:  return g_OUT0;
        case F_H1:    return g_H1;
        case F_EL1:   return g_EL1;
        case F_ER1:   return g_ER1;
        case F_SKIP1: return g_SKIP1;
        case F_OUT1:  return g_OUT1;
        case F_MLPH:  return g_MLPH;
    }
    return nullptr;
}
__device__ __forceinline__ int* IBUF(int id) {
    switch (id) {
        case I_CNT0:  return g_cnt0;
        case I_OFF0:  return g_off0;
        case I_CUR0:  return g_cur0;
        case I_PERM0: return g_perm0;
        case I_CNT1:  return g_cnt1;
        case I_OFF1:  return g_off1;
        case I_CUR1:  return g_cur1;
        case I_PERM1: return g_perm1;
    }
    return nullptr;
}

__device__ __forceinline__ float lrelu(float z) { return z > 0.f ? z : NEG * z; }

// ---------------- bf16 split helpers ----------------
__device__ __forceinline__ void split2(float v0, float v1, uint32_t& hi, uint32_t& lo) {
    uint32_t h;
    asm("cvt.rn.bf16x2.f32 %0, %1, %2;" : "=r"(h) : "f"(v1), "f"(v0));
    float f0 = __uint_as_float(h << 16);
    float f1 = __uint_as_float(h & 0xffff0000u);
    uint32_t l;
    asm("cvt.rn.bf16x2.f32 %0, %1, %2;" : "=r"(l) : "f"(v1 - f1), "f"(v0 - f0));
    hi = h; lo = l;
}
__device__ __forceinline__ void mma_bf16(float* d, const uint32_t* a, const uint32_t* b) {
    asm volatile(
        "mma.sync.aligned.m16n8k16.row.col.f32.bf16.bf16.f32 "
        "{%0,%1,%2,%3}, {%4,%5,%6,%7}, {%8,%9}, {%0,%1,%2,%3};"
        : "+f"(d[0]), "+f"(d[1]), "+f"(d[2]), "+f"(d[3])
        : "r"(a[0]), "r"(a[1]), "r"(a[2]), "r"(a[3]), "r"(b[0]), "r"(b[1]));
}
__device__ __forceinline__ void cp16(uint32_t* dst, const uint32_t* src, bool valid) {
    uint32_t d = (uint32_t)__cvta_generic_to_shared(dst);
    int sz = valid ? 16 : 0;
    asm volatile("cp.async.cg.shared.global [%0], [%1], 16, %2;"
                 :: "r"(d), "l"(src), "r"(sz));
}

// ---------------- operand split kernels ----------------
__global__ void splitA_k(const float* __restrict__ Aext, int Aid, int tot) {
    const float* A = Aext ? Aext : FBUF(Aid);
    for (int idx = blockIdx.x * blockDim.x + threadIdx.x; idx < tot; idx += gridDim.x * blockDim.x) {
        float2 v = *(const float2*)&A[2 * idx];
        uint32_t h, l;
        split2(v.x, v.y, h, l);
        g_ASh[idx] = h;
        g_ASl[idx] = l;
    }
}

__global__ void splitB_k(const float* __restrict__ W, int K) {
    int z = blockIdx.z;
    int K2 = K >> 1;
    const float* Wz = W + (size_t)z * K * HID;
    uint32_t* Bh = g_BSh + (size_t)z * K2 * HID;
    uint32_t* Bl = g_BSl + (size_t)z * K2 * HID;
    int tot = K2 * HID;
    for (int idx = blockIdx.x * blockDim.x + threadIdx.x; idx < tot; idx += gridDim.x * blockDim.x) {
        int k2 = idx >> 7, n = idx & 127;
        float v0 = Wz[(2 * k2    ) * HID + n];
        float v1 = Wz[(2 * k2 + 1) * HID + n];
        uint32_t h, l;
        split2(v0, v1, h, l);
        Bh[idx] = h;
        Bl[idx] = l;
    }
}

// ---------------- tensor-core GEMM, 2-stage cp.async pipeline ----------------
#define APAD2 20
#define BPAD2 132
#define A_ST (128 * APAD2)
#define B_ST (16 * BPAD2)
#define GEMM_SMEM_BYTES ((2 * A_ST * 2 + 2 * B_ST * 2) * 4)

__global__ void __launch_bounds__(256, 2)
mma_gemm2_k(int M, int K2, const float* __restrict__ bias, int Cid,
            long long Bbatch, long long Cbatch)
{
    const uint32_t* Ah = g_ASh;
    const uint32_t* Al = g_ASl;
    const uint32_t* Bh = g_BSh + (size_t)blockIdx.z * Bbatch;
    const uint32_t* Bl = g_BSl + (size_t)blockIdx.z * Bbatch;
    float* C = FBUF(Cid) + (size_t)blockIdx.z * Cbatch;

    extern __shared__ uint32_t smem[];
    uint32_t* AsH = smem;                     // 2 stages x A_ST
    uint32_t* AsL = smem + 2 * A_ST;
    uint32_t* BsH = smem + 4 * A_ST;          // 2 stages x B_ST
    uint32_t* BsL = BsH + 2 * B_ST;

    int tid  = threadIdx.x;
    int warp = tid >> 5, lane = tid & 31;
    int g = lane >> 2, t4 = lane & 3;
    int wr = (warp & 3) * 32;
    int wc = (warp >> 2) * 64;
    int row0 = blockIdx.y * 128;

    float acc[2][8][4];
    #pragma unroll
    for (int mi = 0; mi < 2; mi++)
        #pragma unroll
        for (int ni = 0; ni < 8; ni++)
            #pragma unroll
            for (int q = 0; q < 4; q++) acc[mi][ni][q] = 0.f;

    // stage-issue: loads K-tile kt2 into stage s
    auto issue = [&](int s, int kt2) {
        uint32_t* aH = AsH + s * A_ST;
        uint32_t* aL = AsL + s * A_ST;
        uint32_t* bH = BsH + s * B_ST;
        uint32_t* bL = BsL + s * B_ST;
        #pragma unroll
        for (int l = 0; l < 2; l++) {
            int sl = tid + l * 256;          // 512 uint4 slots for A
            int r  = sl >> 2;
            int c4 = (sl & 3) * 4;
            int rg = row0 + r;
            bool v = rg < M;
            size_t o = (size_t)(v ? rg : 0) * K2 + kt2 + c4;
            cp16(&aH[r * APAD2 + c4], &Ah[o], v);
            cp16(&aL[r * APAD2 + c4], &Al[o], v);
        }
        #pragma unroll
        for (int l = 0; l < 2; l++) {
            int sl = tid + l * 256;          // 512 uint4 slots for B
            int r  = sl >> 5;
            int c4 = (sl & 31) * 4;
            size_t o = (size_t)(kt2 + r) * HID + c4;
            cp16(&bH[r * BPAD2 + c4], &Bh[o], true);
            cp16(&bL[r * BPAD2 + c4], &Bl[o], true);
        }
        asm volatile("cp.async.commit_group;");
    };

    int T = K2 >> 4;     // 16-u32 K-tiles
    issue(0, 0);

    for (int t = 0; t < T; t++) {
        asm volatile("cp.async.wait_group 0;");
        __syncthreads();
        if (t + 1 < T) issue((t + 1) & 1, (t + 1) * 16);

        int s = t & 1;
        const uint32_t* aH = AsH + s * A_ST;
        const uint32_t* aL = AsL + s * A_ST;
        const uint32_t* bH = BsH + s * B_ST;
        const uint32_t* bL = BsL + s * B_ST;

        #pragma unroll
        for (int s16 = 0; s16 < 2; s16++) {
            int ks2 = s16 * 8;
            uint32_t ah[2][4], al[2][4];
            #pragma unroll
            for (int mi = 0; mi < 2; mi++) {
                int r0 = wr + mi * 16 + g;
                ah[mi][0] = aH[(r0    ) * APAD2 + ks2 + t4    ];
                ah[mi][1] = aH[(r0 + 8) * APAD2 + ks2 + t4    ];
                ah[mi][2] = aH[(r0    ) * APAD2 + ks2 + t4 + 4];
                ah[mi][3] = aH[(r0 + 8) * APAD2 + ks2 + t4 + 4];
                al[mi][0] = aL[(r0    ) * APAD2 + ks2 + t4    ];
                al[mi][1] = aL[(r0 + 8) * APAD2 + ks2 + t4    ];
                al[mi][2] = aL[(r0    ) * APAD2 + ks2 + t4 + 4];
                al[mi][3] = aL[(r0 + 8) * APAD2 + ks2 + t4 + 4];
            }
            #pragma unroll
            for (int ni = 0; ni < 8; ni++) {
                int c0 = wc + ni * 8 + g;
                uint32_t bh[2], bl[2];
                bh[0] = bH[(ks2 + t4    ) * BPAD2 + c0];
                bh[1] = bH[(ks2 + t4 + 4) * BPAD2 + c0];
                bl[0] = bL[(ks2 + t4    ) * BPAD2 + c0];
                bl[1] = bL[(ks2 + t4 + 4) * BPAD2 + c0];
                #pragma unroll
                for (int mi = 0; mi < 2; mi++) {
                    mma_bf16(acc[mi][ni], ah[mi], bh);
                    mma_bf16(acc[mi][ni], al[mi], bh);
                    mma_bf16(acc[mi][ni], ah[mi], bl);
                }
            }
        }
        __syncthreads();
    }

    // epilogue
    #pragma unroll
    for (int mi = 0; mi < 2; mi++) {
        int r0 = row0 + wr + mi * 16 + g;
        #pragma unroll
        for (int ni = 0; ni < 8; ni++) {
            int c0 = wc + ni * 8 + t4 * 2;
            float bz0 = bias ? bias[c0] : 0.f;
            float bz1 = bias ? bias[c0 + 1] : 0.f;
            if (r0 < M) {
                float2 v = make_float2(acc[mi][ni][0] + bz0, acc[mi][ni][1] + bz1);
                *(float2*)&C[(size_t)r0 * HID + c0] = v;
            }
            if (r0 + 8 < M) {
                float2 v = make_float2(acc[mi][ni][2] + bz0, acc[mi][ni][3] + bz1);
                *(float2*)&C[(size_t)(r0 + 8) * HID + c0] = v;
            }
        }
    }
}

// ---------------- FFMA SGEMM (final layer, N=153) ----------------
__global__ void __launch_bounds__(256)
sgemm_k(const float* __restrict__ Aext, int Aid,
        const float* __restrict__ Bg, const float* __restrict__ bias,
        float* __restrict__ Cext, int Cid,
        int M, int N, int K, int ldb, int ldc)
{
    const float* A = (Aext ? Aext : FBUF(Aid));
    const float* B = Bg;
    float*       C = (Cext ? Cext : FBUF(Cid));

    __shared__ float As[16][128];
    __shared__ float Bs[16][128];

    int tid  = threadIdx.x;
    int row0 = blockIdx.y * 128;
    int col0 = blockIdx.x * 128;
    int ty = tid >> 4, tx = tid & 15;

    float acc[8][8];
    #pragma unroll
    for (int i = 0; i < 8; i++)
        #pragma unroll
        for (int j = 0; j < 8; j++) acc[i][j] = 0.f;

    for (int kt = 0; kt < K; kt += 16) {
        #pragma unroll
        for (int l = 0; l < 2; l++) {
            int s  = tid + l * 256;
            int r  = s >> 2;
            int c4 = (s & 3) * 4;
            int rg = row0 + r;
            float4 v = make_float4(0.f, 0.f, 0.f, 0.f);
            if (rg < M) v = *(const float4*)&A[(size_t)rg * K + kt + c4];
            As[c4 + 0][r] = v.x; As[c4 + 1][r] = v.y;
            As[c4 + 2][r] = v.z; As[c4 + 3][r] = v.w;
        }
        #pragma unroll
        for (int l = 0; l < 8; l++) {
            int s  = tid + l * 256;
            int kk = s >> 7, cc = s & 127;
            int cg = col0 + cc;
            Bs[kk][cc] = (cg < N) ? B[(size_t)(kt + kk) * ldb + cg] : 0.f;
        }
        __syncthreads();
        #pragma unroll
        for (int kk = 0; kk < 16; kk++) {
            float a[8], b[8];
            *(float4*)&a[0] = *(const float4*)&As[kk][ty * 8];
            *(float4*)&a[4] = *(const float4*)&As[kk][ty * 8 + 4];
            *(float4*)&b[0] = *(const float4*)&Bs[kk][tx * 8];
            *(float4*)&b[4] = *(const float4*)&Bs[kk][tx * 8 + 4];
            #pragma unroll
            for (int i = 0; i < 8; i++)
                #pragma unroll
                for (int j = 0; j < 8; j++) acc[i][j] += a[i] * b[j];
        }
        __syncthreads();
    }
    #pragma unroll
    for (int i = 0; i < 8; i++) {
        int r = row0 + ty * 8 + i;
        if (r >= M) continue;
        #pragma unroll
        for (int j = 0; j < 8; j++) {
            int c = col0 + tx * 8 + j;
            if (c < N) C[(size_t)r * ldc + c] = acc[i][j] + (bias ? bias[c] : 0.f);
        }
    }
}

// ---------------- el/er from H: one warp per (node, relation) ----------------
__global__ void eler_k(int Hid, const float* __restrict__ al, const float* __restrict__ ar,
                       int ELid, int ERid, int n_src, int n_dst)
{
    const float* Hb = FBUF(Hid);
    float* EL = FBUF(ELid);
    float* ER = FBUF(ERid);
    int w    = (blockIdx.x * blockDim.x + threadIdx.x) >> 5;
    int lane = threadIdx.x & 31;
    int total = n_src * TREL;
    if (w >= total) return;
    int j = w / n_src;
    int i = w - j * n_src;

    float4 hv = *(const float4*)&Hb[((size_t)j * n_src + i) * HID + lane * 4];
    float4 av = *(const float4*)&al[j * HID + lane * 4];
    float pl = hv.x * av.x + hv.y * av.y + hv.z * av.z + hv.w * av.w;
    float pr = 0.f;
    if (i < n_dst) {
        float4 rv = *(const float4*)&ar[j * HID + lane * 4];
        pr = hv.x * rv.x + hv.y * rv.y + hv.z * rv.z + hv.w * rv.w;
    }
    #pragma unroll
    for (int o = 4; o >= 1; o >>= 1) {
        pl += __shfl_down_sync(0xffffffffu, pl, o, 8);
        pr += __shfl_down_sync(0xffffffffu, pr, o, 8);
    }
    if ((lane & 7) == 0) {
        int h = lane >> 3;
        EL[(size_t)i * (TREL * HEADS) + j * HEADS + h] = pl;
        if (i < n_dst) ER[(size_t)i * (TREL * HEADS) + j * HEADS + h] = pr;
    }
}

// ---------------- CSR build ----------------
__global__ void zero_i_k(int id, int n) {
    int* p = IBUF(id);
    for (int i = blockIdx.x * blockDim.x + threadIdx.x; i < n; i += gridDim.x * blockDim.x)
        p[i] = 0;
}

__global__ void count_k(const int* __restrict__ dst, int E, int n_dst, int cntid) {
    int j = blockIdx.z;
    int* cnt = IBUF(cntid) + j * n_dst;
    const int* dj = dst + (size_t)j * E;
    for (int e = blockIdx.x * blockDim.x + threadIdx.x; e < E; e += gridDim.x * blockDim.x)
        atomicAdd(&cnt[dj[e]], 1);
}

__global__ void scan_k(int cntid, int offid, int n) {
    __shared__ int sh[1024];
    const int* cnt = IBUF(cntid) + blockIdx.x * n;
    int* off = IBUF(offid) + blockIdx.x * (n + 1);
    int carry = 0;
    for (int base = 0; base < n; base += 1024) {
        int i = base + threadIdx.x;
        int v = (i < n) ? cnt[i] : 0;
        sh[threadIdx.x] = v;
        __syncthreads();
        for (int o = 1; o < 1024; o <<= 1) {
            int t = (threadIdx.x >= o) ? sh[threadIdx.x - o] : 0;
            __syncthreads();
            sh[threadIdx.x] += t;
            __syncthreads();
        }
        if (i < n) off[i] = carry + sh[threadIdx.x] - v;
        int tot = sh[1023];
        __syncthreads();
        carry += tot;
    }
    if (threadIdx.x == 0) off[n] = carry;
}

__global__ void initcur_k(int offid, int curid, int n) {
    const int* off = IBUF(offid);
    int* cur = IBUF(curid);
    int tot = TREL * n;
    for (int idx = blockIdx.x * blockDim.x + threadIdx.x; idx < tot; idx += gridDim.x * blockDim.x) {
        int j = idx / n, d = idx - j * n;
        cur[idx] = off[j * (n + 1) + d];
    }
}

__global__ void fill_k(const int* __restrict__ dst, const int* __restrict__ src,
                       int E, int n_dst, int curid, int permid) {
    int j = blockIdx.z;
    int* cur  = IBUF(curid) + j * n_dst;
    int* perm = IBUF(permid) + (size_t)j * E;
    const int* dj = dst + (size_t)j * E;
    const int* sj = src + (size_t)j * E;
    for (int e = blockIdx.x * blockDim.x + threadIdx.x; e < E; e += gridDim.x * blockDim.x) {
        int pos = atomicAdd(&cur[dj[e]], 1);
        perm[pos] = sj[e];
    }
}

// ---------------- attention aggregation ----------------
__global__ void agg_k(int Hid, int ELid, int ERid,
                      int offid, int permid, int SKIPid, const float* __restrict__ b,
                      int OUTid, int n_src, int n_dst, int E)
{
    const float* Hb = FBUF(Hid);
    const float* EL = FBUF(ELid);
    const float* ER = FBUF(ERid);
    const float* SK = FBUF(SKIPid);
    float* OUTp = FBUF(OUTid);
    const int* off  = IBUF(offid);
    const int* perm = IBUF(permid);

    int w    = (blockIdx.x * blockDim.x + threadIdx.x) >> 5;
    int lane = threadIdx.x & 31;
    if (w >= n_dst) return;
    int d = w;
    int h = lane >> 3;

    float4 acc = *(const float4*)&SK[(size_t)d * HID + lane * 4];
    #pragma unroll
    for (int j = 0; j < TREL; j++) {
        float4 bv = *(const float4*)&b[j * HID + lane * 4];
        acc.x += bv.x; acc.y += bv.y; acc.z += bv.z; acc.w += bv.w;
    }

    for (int j = 0; j < TREL; j++) {
        int s0 = off[j * (n_dst + 1) + d];
        int s1 = off[j * (n_dst + 1) + d + 1];
        if (s1 == s0) continue;
        float erh = ER[(size_t)d * (TREL * HEADS) + j * HEADS + h];
        const int* pj = perm + (size_t)j * E;
        const float* Hj = Hb + (size_t)j * n_src * HID;

        float4 racc = make_float4(0.f, 0.f, 0.f, 0.f);
        float z = 0.f;
        int p = s0;
        for (; p + 3 < s1; p += 4) {
            int sA = pj[p], sB = pj[p + 1], sC = pj[p + 2], sD = pj[p + 3];
            float eA = EL[(size_t)sA * (TREL * HEADS) + j * HEADS + h];
            float eB = EL[(size_t)sB * (TREL * HEADS) + j * HEADS + h];
            float eC = EL[(size_t)sC * (TREL * HEADS) + j * HEADS + h];
            float eD = EL[(size_t)sD * (TREL * HEADS) + j * HEADS + h];
            float4 hA = *(const float4*)&Hj[(size_t)sA * HID + lane * 4];
            float4 hB = *(const float4*)&Hj[(size_t)sB * HID + lane * 4];
            float4 hC = *(const float4*)&Hj[(size_t)sC * HID + lane * 4];
            float4 hD = *(const float4*)&Hj[(size_t)sD * HID + lane * 4];
            float wA = __expf(fminf(lrelu(eA + erh), 80.f));
            float wB = __expf(fminf(lrelu(eB + erh), 80.f));
            float wC = __expf(fminf(lrelu(eC + erh), 80.f));
            float wD = __expf(fminf(lrelu(eD + erh), 80.f));
            z += (wA + wB) + (wC + wD);
            racc.x += wA * hA.x + wB * hB.x + wC * hC.x + wD * hD.x;
            racc.y += wA * hA.y + wB * hB.y + wC * hC.y + wD * hD.y;
            racc.z += wA * hA.z + wB * hB.z + wC * hC.z + wD * hD.z;
            racc.w += wA * hA.w + wB * hB.w + wC * hC.w + wD * hD.w;
        }
        for (; p < s1; p++) {
            int sA = pj[p];
            float eA = EL[(size_t)sA * (TREL * HEADS) + j * HEADS + h];
            float4 hA = *(const float4*)&Hj[(size_t)sA * HID + lane * 4];
            float wA = __expf(fminf(lrelu(eA + erh), 80.f));
            z += wA;
            racc.x += wA * hA.x; racc.y += wA * hA.y;
            racc.z += wA * hA.z; racc.w += wA * hA.w;
        }
        float inv = 1.f / (z + 1e-16f);
        acc.x += racc.x * inv; acc.y += racc.y * inv;
        acc.z += racc.z * inv; acc.w += racc.w * inv;
    }
    *(float4*)&OUTp[(size_t)d * HID + lane * 4] = acc;
}

// ---------------- column statistics + normalize + activation ----------------
__global__ void zstat_k() {
    int t = threadIdx.x;
    if (t < HID) { g_sum[t] = 0.0; g_sq[t] = 0.0; }
}

__global__ void colstat_k(int Xid, int n) {
    const float* X = FBUF(Xid);
    int c = threadIdx.x;
    float s = 0.f, q = 0.f;
    for (int r = blockIdx.x * 2; r < n; r += gridDim.x * 2) {
        float v = X[(size_t)r * HID + c];
        s += v; q += v * v;
        int r2 = r + 1;
        if (r2 < n) {
            float v2 = X[(size_t)r2 * HID + c];
            s += v2; q += v2 * v2;
        }
    }
    atomicAdd(&g_sum[c], (double)s);
    atomicAdd(&g_sq [c], (double)q);
}

__global__ void norm_k(int Xid, int Yid, const float* __restrict__ g,
                       const float* __restrict__ be, int n, int act)
{
    const float* X = FBUF(Xid);
    float* Y = FBUF(Yid);
    int c = threadIdx.x;
    double mean = g_sum[c] / (double)n;
    double var  = g_sq[c] / (double)n - mean * mean;
    float fm = (float)mean;
    float sc = (float)(1.0 / sqrt(var + EPSV));
    float gg = g[c] * sc;
    float bb = be[c];
    for (int r = blockIdx.x; r < n; r += gridDim.x) {
        float v = (X[(size_t)r * HID + c] - fm) * gg + bb;
        float y;
        if (act == 0) y = v > 0.f ? v : expm1f(v);
        else          y = v > 0.f ? v : 0.f;
        Y[(size_t)r * HID + c] = y;
    }
}

static inline int cdiv(int a, int b) { return (a + b - 1) / b; }

// ---------------- launcher ----------------
extern "C" void kernel_launch(void* const* d_in, const int* in_sizes, int n_in,
                              void* d_out, int out_size)
{
    const float* x    = (const float*)d_in[0];
    const float* W0   = (const float*)d_in[1];
    const float* al0  = (const float*)d_in[2];
    const float* ar0  = (const float*)d_in[3];
    const float* b0   = (const float*)d_in[4];
    const float* Ws0  = (const float*)d_in[5];
    const float* bs0  = (const float*)d_in[6];
    const float* g0   = (const float*)d_in[7];
    const float* be0  = (const float*)d_in[8];
    const float* W1   = (const float*)d_in[9];
    const float* al1  = (const float*)d_in[10];
    const float* ar1  = (const float*)d_in[11];
    const float* b1   = (const float*)d_in[12];
    const float* Ws1  = (const float*)d_in[13];
    const float* bs1  = (const float*)d_in[14];
    const float* g1   = (const float*)d_in[15];
    const float* be1  = (const float*)d_in[16];
    const float* Wm1  = (const float*)d_in[17];
    const float* bm1  = (const float*)d_in[18];
    const float* gm   = (const float*)d_in[19];
    const float* bem  = (const float*)d_in[20];
    const float* Wm2  = (const float*)d_in[21];
    const float* bm2  = (const float*)d_in[22];
    const int*   src0 = (const int*)d_in[23];
    const int*   dst0 = (const int*)d_in[24];
    const int*   src1 = (const int*)d_in[25];
    const int*   dst1 = (const int*)d_in[26];
    float* out = (float*)d_out;

    // Unconditional (no static guards) — deterministic, not captured into the graph.
    cudaFuncSetAttribute(mma_gemm2_k, cudaFuncAttributeMaxDynamicSharedMemorySize,
                         GEMM_SMEM_BYTES);

    // ===== Layer 0 ===== (launch order: big GEMM is 4th -> profiled slot)
    splitB_k<<<dim3(64, 1, TREL), 256>>>(W0, INFEAT);
    splitA_k<<<2048, 256>>>(x, -1, NSRC0 * (INFEAT / 2));
    zero_i_k<<<256, 256>>>(I_CNT0, TREL * NDST0);
    mma_gemm2_k<<<dim3(1, cdiv(NSRC0, 128), TREL), 256, GEMM_SMEM_BYTES>>>(   // H0 = x @ W0[j]
        NSRC0, INFEAT / 2, nullptr, F_H0,
        (long long)(INFEAT / 2) * HID, (long long)NSRC0 * HID);
    count_k<<<dim3(1024, 1, TREL), 256>>>(dst0, E0, NDST0, I_CNT0);
    scan_k<<<TREL, 1024>>>(I_CNT0, I_OFF0, NDST0);
    splitB_k<<<dim3(64, 1, 1), 256>>>(Ws0, INFEAT);
    mma_gemm2_k<<<dim3(1, cdiv(NDST0, 128), 1), 256, GEMM_SMEM_BYTES>>>(      // SKIP0
        NDST0, INFEAT / 2, bs0, F_SKIP0, 0LL, 0LL);
    eler_k<<<cdiv(NSRC0 * TREL * 32, 256), 256>>>(F_H0, al0, ar0, F_EL0, F_ER0, NSRC0, NDST0);
    initcur_k<<<256, 256>>>(I_OFF0, I_CUR0, NDST0);
    fill_k<<<dim3(1024, 1, TREL), 256>>>(dst0, src0, E0, NDST0, I_CUR0, I_PERM0);
    agg_k<<<cdiv(NDST0 * 32, 256), 256>>>(F_H0, F_EL0, F_ER0, I_OFF0, I_PERM0,
                                          F_SKIP0, b0, F_OUT0, NSRC0, NDST0, E0);
    zstat_k<<<1, 128>>>();
    colstat_k<<<512, 128>>>(F_OUT0, NDST0);
    norm_k<<<512, 128>>>(F_OUT0, F_OUT0, g0, be0, NDST0, 0);

    // ===== Layer 1 =====
    splitA_k<<<1024, 256>>>(nullptr, F_OUT0, NDST0 * (HID / 2));
    splitB_k<<<dim3(32, 1, TREL), 256>>>(W1, HID);
    mma_gemm2_k<<<dim3(1, cdiv(NDST0, 128), TREL), 256, GEMM_SMEM_BYTES>>>(   // H1
        NDST0, HID / 2, nullptr, F_H1,
        (long long)(HID / 2) * HID, (long long)NDST0 * HID);
    splitB_k<<<dim3(32, 1, 1), 256>>>(Ws1, HID);
    mma_gemm2_k<<<dim3(1, cdiv(NDST1, 128), 1), 256, GEMM_SMEM_BYTES>>>(      // SKIP1
        NDST1, HID / 2, bs1, F_SKIP1, 0LL, 0LL);
    eler_k<<<cdiv(NDST0 * TREL * 32, 256), 256>>>(F_H1, al1, ar1, F_EL1, F_ER1, NDST0, NDST1);
    zero_i_k<<<256, 256>>>(I_CNT1, TREL * NDST1);
    count_k<<<dim3(512, 1, TREL), 256>>>(dst1, E1, NDST1, I_CNT1);
    scan_k<<<TREL, 1024>>>(I_CNT1, I_OFF1, NDST1);
    initcur_k<<<256, 256>>>(I_OFF1, I_CUR1, NDST1);
    fill_k<<<dim3(512, 1, TREL), 256>>>(dst1, src1, E1, NDST1, I_CUR1, I_PERM1);
    agg_k<<<cdiv(NDST1 * 32, 256), 256>>>(F_H1, F_EL1, F_ER1, I_OFF1, I_PERM1,
                                          F_SKIP1, b1, F_OUT1, NDST0, NDST1, E1);
    zstat_k<<<1, 128>>>();
    colstat_k<<<512, 128>>>(F_OUT1, NDST1);
    norm_k<<<512, 128>>>(F_OUT1, F_OUT1, g1, be1, NDST1, 0);

    // ===== MLP =====
    splitA_k<<<512, 256>>>(nullptr, F_OUT1, NDST1 * (HID / 2));
    splitB_k<<<dim3(32, 1, 1), 256>>>(Wm1, HID);
    mma_gemm2_k<<<dim3(1, cdiv(NDST1, 128), 1), 256, GEMM_SMEM_BYTES>>>(
        NDST1, HID / 2, bm1, F_MLPH, 0LL, 0LL);
    zstat_k<<<1, 128>>>();
    colstat_k<<<512, 128>>>(F_MLPH, NDST1);
    norm_k<<<512, 128>>>(F_MLPH, F_MLPH, gm, bem, NDST1, 1);
    sgemm_k<<<dim3(cdiv(OUTF, 128), cdiv(NDST1, 128), 1), 256>>>(
        nullptr, F_MLPH, Wm2, bm2, out, -1,
        NDST1, OUTF, HID, OUTF, OUTF);
}